// round 1
// baseline (speedup 1.0000x reference)
#include <cuda_runtime.h>
#include <math.h>

#define Bn 32
#define N1 512
#define N2 512
#define Dd 128
#define Mw 256
#define Kd 96
#define GAMMAc 0.1f
#define BARRIERc 10000.0f

// exp((m-x)/gamma) = exp2((m-x)*IG2);  gamma*ln(s) = GLN2*log2(s)
#define IG2 14.4269504088896f   /* log2(e)/gamma */
#define GLN2 0.069314718055995f /* gamma*ln(2)   */

__device__ float g_T1[Bn], g_T2[Bn];
__device__ float g_s1at[Bn][Mw][Dd];
__device__ float g_tau[Bn][Mw][Kd];
__device__ float g_node[Bn][Mw][Kd];
__device__ float g_alpha[Bn][Mw][Kd];
__device__ float g_beta[Bn][Mw][Kd];

// ---------------- kernel 0: per-batch maxima of time vectors ----------------
__global__ void k0_maxes(const float* __restrict__ t1, const float* __restrict__ t2) {
    int b = blockIdx.x, t = threadIdx.x;  // 256 threads
    float m1 = -3.4e38f, m2 = -3.4e38f;
    for (int i = t; i < N1; i += 256) m1 = fmaxf(m1, t1[b * N1 + i]);
    for (int i = t; i < N2; i += 256) m2 = fmaxf(m2, t2[b * N2 + i]);
    __shared__ float s1[8], s2[8];
    for (int o = 16; o; o >>= 1) {
        m1 = fmaxf(m1, __shfl_xor_sync(0xffffffffu, m1, o));
        m2 = fmaxf(m2, __shfl_xor_sync(0xffffffffu, m2, o));
    }
    if ((t & 31) == 0) { s1[t >> 5] = m1; s2[t >> 5] = m2; }
    __syncthreads();
    if (t == 0) {
        float a = s1[0], c = s2[0];
        for (int w = 1; w < 8; w++) { a = fmaxf(a, s1[w]); c = fmaxf(c, s2[w]); }
        g_T1[b] = a; g_T2[b] = c;
    }
}

// ---------------- kernel 1: s1 interpolation + tau grid ----------------
__global__ void k1_prep(const float* __restrict__ s1f, const float* __restrict__ glb_lb,
                        const float* __restrict__ glb_ub, const float* __restrict__ tw) {
    int m = blockIdx.x, b = blockIdx.y, t = threadIdx.x;  // 128 threads
    float T1 = g_T1[b], T2 = g_T2[b];
    float pos = tw[b * Mw + m] / T1;
    float x = fminf(fmaxf(pos, 0.f), 1.f) * (float)(N1 - 1);
    int i0 = min(max((int)x, 0), N1 - 2);
    float w = x - (float)i0;
    const float* r0 = s1f + ((size_t)b * N1 + i0) * Dd;
    float f0 = r0[t], f1 = r0[Dd + t];
    g_s1at[b][m][t] = f0 * (1.f - w) + f1 * w;
    if (t < Kd) {
        float lb = glb_lb[b * Mw + m] * T2;
        float ub = glb_ub[b * Mw + m] * T2;
        g_tau[b][m][t] = lb + (ub - lb) * ((float)t / (float)(Kd - 1));
    }
}

// ---------------- kernel 2: node costs (warp-per-k, loop m, cache s2 rows) ----------------
__global__ void k2_node(const float* __restrict__ s2f, const float* __restrict__ tw) {
    int b = blockIdx.y;
    int wq = threadIdx.x >> 5, lane = threadIdx.x & 31;
    int k = blockIdx.x * 4 + wq;
    float T2 = g_T2[b];
    float invT2 = 1.f / T2;
    const float* s2b = s2f + (size_t)b * N2 * Dd;
    int i0p = -1;
    float4 f0v = make_float4(0.f, 0.f, 0.f, 0.f), f1v = f0v;
    for (int m = 0; m < Mw; m++) {
        float tk = g_tau[b][m][k];
        float pos = tk * invT2;
        float x = fminf(fmaxf(pos, 0.f), 1.f) * (float)(N2 - 1);
        int i0 = min(max((int)x, 0), N2 - 2);
        float w = x - (float)i0;
        if (i0 != i0p) {
            f0v = *((const float4*)(s2b + (size_t)i0 * Dd) + lane);
            f1v = *((const float4*)(s2b + (size_t)(i0 + 1) * Dd) + lane);
            i0p = i0;
        }
        float4 s1v = *((const float4*)(&g_s1at[b][m][0]) + lane);
        float d0 = s1v.x - (f0v.x + w * (f1v.x - f0v.x));
        float d1 = s1v.y - (f0v.y + w * (f1v.y - f0v.y));
        float d2 = s1v.z - (f0v.z + w * (f1v.z - f0v.z));
        float d3 = s1v.w - (f0v.w + w * (f1v.w - f0v.w));
        float acc = fmaf(d0, d0, fmaf(d1, d1, fmaf(d2, d2, d3 * d3)));
        for (int o = 16; o; o >>= 1) acc += __shfl_xor_sync(0xffffffffu, acc, o);
        if (lane == 0) {
            float twm = tw[b * Mw + m];
            float wt = 0.f;
            if (m > 0) wt += twm - tw[b * Mw + m - 1];
            if (m < Mw - 1) wt += tw[b * Mw + m + 1] - twm;
            wt *= 0.5f;
            float node = acc * wt;
            if (m == 0) node += BARRIERc * tk * tk;
            if (m == Mw - 1) { float dd = tk - T2; node += BARRIERc * dd * dd; }
            g_node[b][m][k] = node;
        }
    }
}

// ---------------- edge cost ----------------
__device__ __forceinline__ float edge_fn(float slope, float gub, float rwd) {
    float d1 = slope - 1.f;
    float n1 = fminf(slope, 0.f);
    float r2 = fmaxf(slope - gub, 0.f);
    float pen = fmaf(n1, n1, r2 * r2);
    return fmaf(BARRIERc, pen, rwd * d1 * d1);
}

// lower bound (first index with v >= A) over ascending smem array
__device__ __forceinline__ int lbound(const float* s, float A) {
    int lo = 0, hi = Kd;
    while (lo < hi) { int md = (lo + hi) >> 1; if (s[md] < A) lo = md + 1; else hi = md; }
    return lo;
}
// first index with v > B
__device__ __forceinline__ int ubound(const float* s, float B) {
    int lo = 0, hi = Kd;
    while (lo < hi) { int md = (lo + hi) >> 1; if (s[md] <= B) lo = md + 1; else hi = md; }
    return lo;
}

// ---------------- kernel 3: windowed soft-min scans (dir=0 fwd, 1 bwd) ----------------
__global__ void k3_scan(const float* __restrict__ tw, const float* __restrict__ reg_wt,
                        const float* __restrict__ lgu) {
    int dir = blockIdx.x, b = blockIdx.y;
    int t = threadIdx.x;  // 96 threads
    int lane = t & 31, wq = t >> 5;
    __shared__ float s_a[Kd], s_t[Kd], s_mn[3], s_mx[3];
    float rw = reg_wt[b];
    float gub = lgu[b];

    if (dir == 0) {
        // forward: a_{i+1}[k] = node[i+1][k] + softmin_j(a_i[j] + e_i[j,k])
        float a = g_node[b][0][t];
        g_alpha[b][0][t] = a;
        s_a[t] = a;
        s_t[t] = g_tau[b][0][t];
        float mn = a, mx = a;
        for (int o = 16; o; o >>= 1) {
            mn = fminf(mn, __shfl_xor_sync(0xffffffffu, mn, o));
            mx = fmaxf(mx, __shfl_xor_sync(0xffffffffu, mx, o));
        }
        if (lane == 0) { s_mn[wq] = mn; s_mx[wq] = mx; }
        __syncthreads();
        float twp = tw[b * Mw];
        for (int i = 0; i < Mw - 1; i++) {
            float tn = g_tau[b][i + 1][t];
            float nn = g_node[b][i + 1][t];
            float twn = tw[b * Mw + i + 1];
            float dtw = twn - twp; twp = twn;
            float inv = 1.f / dtw;
            float rwd = rw * dtw;
            float mina = fminf(fminf(s_mn[0], s_mn[1]), s_mn[2]);
            float maxa = fmaxf(fmaxf(s_mx[0], s_mx[1]), s_mx[2]);
            // skip j only when edge >= spread + 15  (exp(-15/gamma)=e^-150 -> 0.0f exactly)
            float marg = sqrtf((maxa - mina + 15.f) * (1.f / BARRIERc));
            float A = tn - (gub + marg) * dtw;
            float Bv = tn + marg * dtw;
            int jlo = lbound(s_t, A);
            int jhi = ubound(s_t, Bv) - 1;
            if (jhi < jlo) { int c = min(Kd - 1, max(0, jlo)); jlo = max(0, c - 1); jhi = min(Kd - 1, c + 1); }
            float mval = 3.402823466e38f, ssum = 0.f;
            for (int j = jlo; j <= jhi; j++) {
                float slope = (tn - s_t[j]) * inv;
                float e = edge_fn(slope, gub, rwd);
                float x = s_a[j] + e;
                float dlt = x - mval;
                float tt = exp2f(-fabsf(dlt) * IG2);
                if (dlt < 0.f) { ssum = fmaf(ssum, tt, 1.f); mval = x; }
                else           { ssum += tt; }
            }
            float anew = nn + mval - GLN2 * __log2f(ssum);
            g_alpha[b][i + 1][t] = anew;
            float mn2 = anew, mx2 = anew;
            for (int o = 16; o; o >>= 1) {
                mn2 = fminf(mn2, __shfl_xor_sync(0xffffffffu, mn2, o));
                mx2 = fmaxf(mx2, __shfl_xor_sync(0xffffffffu, mx2, o));
            }
            __syncthreads();
            s_a[t] = anew; s_t[t] = tn;
            if (lane == 0) { s_mn[wq] = mn2; s_mx[wq] = mx2; }
            __syncthreads();
        }
    } else {
        // backward: beta_i[j] = softmin_k(e_i[j,k] + node[i+1][k] + beta_{i+1}[k])
        g_beta[b][Mw - 1][t] = 0.f;
        float c0 = g_node[b][Mw - 1][t];  // c[k] = node[255] + 0
        s_a[t] = c0;
        s_t[t] = g_tau[b][Mw - 1][t];
        float mn = c0, mx = c0;
        for (int o = 16; o; o >>= 1) {
            mn = fminf(mn, __shfl_xor_sync(0xffffffffu, mn, o));
            mx = fmaxf(mx, __shfl_xor_sync(0xffffffffu, mx, o));
        }
        if (lane == 0) { s_mn[wq] = mn; s_mx[wq] = mx; }
        __syncthreads();
        for (int i = Mw - 2; i >= 0; i--) {
            float tj = g_tau[b][i][t];
            float twl = tw[b * Mw + i], twh = tw[b * Mw + i + 1];
            float dtw = twh - twl;
            float inv = 1.f / dtw;
            float rwd = rw * dtw;
            float mina = fminf(fminf(s_mn[0], s_mn[1]), s_mn[2]);
            float maxa = fmaxf(fmaxf(s_mx[0], s_mx[1]), s_mx[2]);
            float marg = sqrtf((maxa - mina + 15.f) * (1.f / BARRIERc));
            float A = tj - marg * dtw;
            float Bv = tj + (gub + marg) * dtw;
            int klo = lbound(s_t, A);
            int khi = ubound(s_t, Bv) - 1;
            if (khi < klo) { int c = min(Kd - 1, max(0, klo)); klo = max(0, c - 1); khi = min(Kd - 1, c + 1); }
            float mval = 3.402823466e38f, ssum = 0.f;
            for (int kk = klo; kk <= khi; kk++) {
                float slope = (s_t[kk] - tj) * inv;
                float e = edge_fn(slope, gub, rwd);
                float x = s_a[kk] + e;
                float dlt = x - mval;
                float tt = exp2f(-fabsf(dlt) * IG2);
                if (dlt < 0.f) { ssum = fmaf(ssum, tt, 1.f); mval = x; }
                else           { ssum += tt; }
            }
            float bnew = mval - GLN2 * __log2f(ssum);
            g_beta[b][i][t] = bnew;
            float cn = g_node[b][i][t] + bnew;  // c for step i-1 uses node[i]
            float mn2 = cn, mx2 = cn;
            for (int o = 16; o; o >>= 1) {
                mn2 = fminf(mn2, __shfl_xor_sync(0xffffffffu, mn2, o));
                mx2 = fmaxf(mx2, __shfl_xor_sync(0xffffffffu, mx2, o));
            }
            __syncthreads();
            s_a[t] = cn; s_t[t] = tj;
            if (lane == 0) { s_mn[wq] = mn2; s_mx[wq] = mx2; }
            __syncthreads();
        }
    }
}

// ---------------- kernel 4: softmax over k, expectation of tau ----------------
__global__ void k4_out(float* __restrict__ out) {
    int m = blockIdx.x, b = blockIdx.y, t = threadIdx.x;  // 96 threads
    int lane = t & 31, wq = t >> 5;
    __shared__ float sm[3], sp[3], spt[3];
    float v = g_alpha[b][m][t] + g_beta[b][m][t];
    float tau = g_tau[b][m][t];
    float mn = v;
    for (int o = 16; o; o >>= 1) mn = fminf(mn, __shfl_xor_sync(0xffffffffu, mn, o));
    if (lane == 0) sm[wq] = mn;
    __syncthreads();
    float vmin = fminf(fminf(sm[0], sm[1]), sm[2]);
    float p = exp2f((vmin - v) * IG2);
    float ps = p, pts = p * tau;
    for (int o = 16; o; o >>= 1) {
        ps += __shfl_xor_sync(0xffffffffu, ps, o);
        pts += __shfl_xor_sync(0xffffffffu, pts, o);
    }
    if (lane == 0) { sp[wq] = ps; spt[wq] = pts; }
    __syncthreads();
    if (t == 0) {
        float S = sp[0] + sp[1] + sp[2];
        float ST = spt[0] + spt[1] + spt[2];
        out[b * Mw + m] = ST / S;
    }
}

extern "C" void kernel_launch(void* const* d_in, const int* in_sizes, int n_in,
                              void* d_out, int out_size) {
    const float* s1f    = (const float*)d_in[0];
    const float* s2f    = (const float*)d_in[1];
    const float* regw   = (const float*)d_in[2];
    const float* glb_lb = (const float*)d_in[3];
    const float* glb_ub = (const float*)d_in[4];
    const float* lgu    = (const float*)d_in[5];
    const float* t1     = (const float*)d_in[6];
    const float* t2     = (const float*)d_in[7];
    const float* twf    = (const float*)d_in[8];
    float* out = (float*)d_out;

    k0_maxes<<<Bn, 256>>>(t1, t2);
    k1_prep<<<dim3(Mw, Bn), Dd>>>(s1f, glb_lb, glb_ub, twf);
    k2_node<<<dim3(Kd / 4, Bn), 128>>>(s2f, twf);
    k3_scan<<<dim3(2, Bn), Kd>>>(twf, regw, lgu);
    k4_out<<<dim3(Mw, Bn), Kd>>>(out);
}

// round 2
// speedup vs baseline: 1.5425x; 1.5425x over previous
#include <cuda_runtime.h>
#include <math.h>

#define Bn 32
#define N1 512
#define N2 512
#define Dd 128
#define Mw 256
#define Kd 96
#define BARRIERc 10000.0f

// exp((m-x)/gamma) = exp2((m-x)*IG2);  gamma*ln(s) = GLN2*log2(s)
#define IG2 14.4269504088896f   /* log2(e)/gamma */
#define GLN2 0.069314718055995f /* gamma*ln(2)   */

__device__ float g_T1[Bn], g_T2[Bn];
__device__ float g_s1at[Bn][Mw][Dd];
__device__ float g_node[Bn][Mw][Kd];
__device__ float g_alpha[Bn][Mw][Kd];
__device__ float g_beta[Bn][Mw][Kd];

// monotone float <-> orderable-uint mapping (for REDUX min/max on floats)
__device__ __forceinline__ unsigned f2o(float x) {
    unsigned u = __float_as_uint(x);
    return (u & 0x80000000u) ? ~u : (u | 0x80000000u);
}
__device__ __forceinline__ float o2f(unsigned v) {
    return __uint_as_float((v & 0x80000000u) ? (v ^ 0x80000000u) : ~v);
}

// ---------------- kernel 0: per-batch maxima of time vectors ----------------
__global__ void k0_maxes(const float* __restrict__ t1, const float* __restrict__ t2) {
    int b = blockIdx.x, t = threadIdx.x;  // 256 threads
    float m1 = -3.4e38f, m2 = -3.4e38f;
    for (int i = t; i < N1; i += 256) m1 = fmaxf(m1, t1[b * N1 + i]);
    for (int i = t; i < N2; i += 256) m2 = fmaxf(m2, t2[b * N2 + i]);
    __shared__ float s1[8], s2[8];
    for (int o = 16; o; o >>= 1) {
        m1 = fmaxf(m1, __shfl_xor_sync(0xffffffffu, m1, o));
        m2 = fmaxf(m2, __shfl_xor_sync(0xffffffffu, m2, o));
    }
    if ((t & 31) == 0) { s1[t >> 5] = m1; s2[t >> 5] = m2; }
    __syncthreads();
    if (t == 0) {
        float a = s1[0], c = s2[0];
        for (int w = 1; w < 8; w++) { a = fmaxf(a, s1[w]); c = fmaxf(c, s2[w]); }
        g_T1[b] = a; g_T2[b] = c;
    }
}

// ---------------- kernel 1: s1 interpolation at warp times ----------------
__global__ void k1_prep(const float* __restrict__ s1f, const float* __restrict__ tw) {
    int m = blockIdx.x, b = blockIdx.y, t = threadIdx.x;  // 128 threads
    float T1 = g_T1[b];
    float pos = tw[b * Mw + m] / T1;
    float x = fminf(fmaxf(pos, 0.f), 1.f) * (float)(N1 - 1);
    int i0 = min(max((int)x, 0), N1 - 2);
    float w = x - (float)i0;
    const float* r0 = s1f + ((size_t)b * N1 + i0) * Dd;
    float f0 = r0[t], f1 = r0[Dd + t];
    g_s1at[b][m][t] = f0 * (1.f - w) + f1 * w;
}

// ---------------- kernel 2: node costs (warp-per-k, 4-m ILP batch) ----------------
__global__ void k2_node(const float* __restrict__ s2f, const float* __restrict__ glb_lb,
                        const float* __restrict__ glb_ub, const float* __restrict__ tw) {
    int b = blockIdx.y;
    int wq = threadIdx.x >> 5, lane = threadIdx.x & 31;
    int k = blockIdx.x * 8 + wq;
    __shared__ float s_lb[Mw], s_w[Mw], s_tw[Mw];
    float T2 = g_T2[b];
    for (int i = threadIdx.x; i < Mw; i += 256) {
        float lb = glb_lb[b * Mw + i] * T2;
        float ub = glb_ub[b * Mw + i] * T2;
        s_lb[i] = lb; s_w[i] = ub - lb; s_tw[i] = tw[b * Mw + i];
    }
    __syncthreads();
    float frk = (float)k / 95.0f;
    float invT2 = 1.f / T2;
    const float* s2b = s2f + (size_t)b * N2 * Dd;
    int i0p = -1;
    float4 f0v = make_float4(0.f, 0.f, 0.f, 0.f), f1v = f0v;
    for (int m0 = 0; m0 < Mw; m0 += 4) {
        float acc[4], tks[4];
        #pragma unroll
        for (int u = 0; u < 4; u++) {
            int m = m0 + u;
            float tk = s_lb[m] + s_w[m] * frk;
            tks[u] = tk;
            float x = fminf(fmaxf(tk * invT2, 0.f), 1.f) * (float)(N2 - 1);
            int i0 = min(max((int)x, 0), N2 - 2);
            float w = x - (float)i0;
            if (i0 != i0p) {
                f0v = *((const float4*)(s2b + (size_t)i0 * Dd) + lane);
                f1v = *((const float4*)(s2b + (size_t)(i0 + 1) * Dd) + lane);
                i0p = i0;
            }
            float4 s1v = *((const float4*)(&g_s1at[b][m][0]) + lane);
            float d0 = s1v.x - (f0v.x + w * (f1v.x - f0v.x));
            float d1 = s1v.y - (f0v.y + w * (f1v.y - f0v.y));
            float d2 = s1v.z - (f0v.z + w * (f1v.z - f0v.z));
            float d3 = s1v.w - (f0v.w + w * (f1v.w - f0v.w));
            acc[u] = fmaf(d0, d0, fmaf(d1, d1, fmaf(d2, d2, d3 * d3)));
        }
        // 4 interleaved butterflies (latency amortized 4x)
        for (int o = 16; o; o >>= 1) {
            #pragma unroll
            for (int u = 0; u < 4; u++)
                acc[u] += __shfl_xor_sync(0xffffffffu, acc[u], o);
        }
        if (lane == 0) {
            #pragma unroll
            for (int u = 0; u < 4; u++) {
                int m = m0 + u;
                float twm = s_tw[m];
                float wt = 0.f;
                if (m > 0) wt += twm - s_tw[m - 1];
                if (m < Mw - 1) wt += s_tw[m + 1] - twm;
                wt *= 0.5f;
                float node = acc[u] * wt;
                float tk = tks[u];
                if (m == 0) node += BARRIERc * tk * tk;
                if (m == Mw - 1) { float dd = tk - T2; node += BARRIERc * dd * dd; }
                g_node[b][m][k] = node;
            }
        }
    }
}

// ---------------- edge cost ----------------
__device__ __forceinline__ float edge_fn(float slope, float gub, float rwd) {
    float d1 = slope - 1.f;
    float n1 = fminf(slope, 0.f);
    float r2 = fmaxf(slope - gub, 0.f);
    float pen = fmaf(n1, n1, r2 * r2);
    return fmaf(BARRIERc, pen, rwd * d1 * d1);
}

// ---------------- kernel 3: single-warp windowed soft-min scans ----------------
__global__ void k3_scan(const float* __restrict__ tw, const float* __restrict__ reg_wt,
                        const float* __restrict__ lgu, const float* __restrict__ glb_lb,
                        const float* __restrict__ glb_ub) {
    int dir = blockIdx.x, b = blockIdx.y;
    int lane = threadIdx.x;  // 32 threads = 1 warp
    __shared__ float s_lb[Mw], s_w[Mw], s_tw[Mw], s_frac[Kd], s_a[2][Kd];
    float T2 = g_T2[b];
    for (int i = lane; i < Mw; i += 32) {
        float lb = glb_lb[b * Mw + i] * T2;
        float ub = glb_ub[b * Mw + i] * T2;
        s_lb[i] = lb; s_w[i] = ub - lb; s_tw[i] = tw[b * Mw + i];
    }
    for (int i = lane; i < Kd; i += 32) s_frac[i] = (float)i / 95.0f;
    __syncwarp();
    float rw = reg_wt[b], gub = lgu[b];
    int kk[3]; float fr[3];
    #pragma unroll
    for (int r = 0; r < 3; r++) { kk[r] = lane + 32 * r; fr[r] = s_frac[kk[r]]; }

    if (dir == 0) {
        // forward: a_{i+1}[k] = node[i+1][k] + softmin_j(a_i[j] + e_i[j,k])
        float a[3], nn[3];
        #pragma unroll
        for (int r = 0; r < 3; r++) {
            a[r] = g_node[b][0][kk[r]];
            g_alpha[b][0][kk[r]] = a[r];
            s_a[0][kk[r]] = a[r];
        }
        float l3 = fminf(fminf(a[0], a[1]), a[2]);
        float h3 = fmaxf(fmaxf(a[0], a[1]), a[2]);
        float mina = o2f(__reduce_min_sync(0xffffffffu, f2o(l3)));
        float maxa = o2f(__reduce_max_sync(0xffffffffu, f2o(h3)));
        #pragma unroll
        for (int r = 0; r < 3; r++) nn[r] = g_node[b][1][kk[r]];
        __syncwarp();
        int cur = 0;
        float lbp = s_lb[0], wp = s_w[0], twp = s_tw[0];
        for (int i = 0; i < Mw - 1; i++) {
            float lbn = s_lb[i + 1], wn = s_w[i + 1], twn = s_tw[i + 1];
            float dtw = twn - twp;
            float invd = 1.f / dtw;
            float rwd = rw * dtw;
            float nn2[3];
            if (i + 2 < Mw) {
                #pragma unroll
                for (int r = 0; r < 3; r++) nn2[r] = g_node[b][i + 2][kk[r]];
            }
            float marg = sqrtf((maxa - mina + 15.f) * (1.f / BARRIERc));
            float inv95wp = __fdividef(95.0f, wp);
            bool degen = !(wp > 0.f);
            float anew[3];
            #pragma unroll
            for (int r = 0; r < 3; r++) {
                float tnk = lbn + wn * fr[r];
                float A = tnk - (gub + marg) * dtw;
                float Bv = tnk + marg * dtw;
                int jlo = max(0, (int)ceilf((A - lbp) * inv95wp));
                int jhi = min(Kd - 1, (int)floorf((Bv - lbp) * inv95wp));
                if (degen) { jlo = 0; jhi = Kd - 1; }
                if (jhi < jlo) { int c = min(Kd - 1, max(0, jlo)); jlo = max(0, c - 1); jhi = min(Kd - 1, c + 1); }
                float mval = 3.402823466e38f, ssum = 0.f;
                for (int j = jlo; j <= jhi; j++) {
                    float tpj = lbp + wp * s_frac[j];
                    float slope = (tnk - tpj) * invd;
                    float e = edge_fn(slope, gub, rwd);
                    float x = s_a[cur][j] + e;
                    float dlt = x - mval;
                    float tt = exp2f(-fabsf(dlt) * IG2);
                    if (dlt < 0.f) { ssum = fmaf(ssum, tt, 1.f); mval = x; }
                    else           { ssum += tt; }
                }
                anew[r] = nn[r] + mval - GLN2 * __log2f(ssum);
            }
            float l = fminf(fminf(anew[0], anew[1]), anew[2]);
            float h = fmaxf(fmaxf(anew[0], anew[1]), anew[2]);
            mina = o2f(__reduce_min_sync(0xffffffffu, f2o(l)));
            maxa = o2f(__reduce_max_sync(0xffffffffu, f2o(h)));
            #pragma unroll
            for (int r = 0; r < 3; r++) {
                s_a[cur ^ 1][kk[r]] = anew[r];
                g_alpha[b][i + 1][kk[r]] = anew[r];
                nn[r] = nn2[r];
            }
            __syncwarp();
            cur ^= 1;
            lbp = lbn; wp = wn; twp = twn;
        }
    } else {
        // backward: beta_i[j] = softmin_k(e_i[j,k] + node[i+1][k] + beta_{i+1}[k])
        float c[3];
        #pragma unroll
        for (int r = 0; r < 3; r++) {
            g_beta[b][Mw - 1][kk[r]] = 0.f;
            c[r] = g_node[b][Mw - 1][kk[r]];
            s_a[0][kk[r]] = c[r];
        }
        float l3 = fminf(fminf(c[0], c[1]), c[2]);
        float h3 = fmaxf(fmaxf(c[0], c[1]), c[2]);
        float mina = o2f(__reduce_min_sync(0xffffffffu, f2o(l3)));
        float maxa = o2f(__reduce_max_sync(0xffffffffu, f2o(h3)));
        __syncwarp();
        int cur = 0;
        float lbp = s_lb[Mw - 1], wp = s_w[Mw - 1], twp = s_tw[Mw - 1];  // grid at i+1
        for (int i = Mw - 2; i >= 0; i--) {
            float lbj = s_lb[i], wj = s_w[i], twj = s_tw[i];
            float dtw = twp - twj;
            float invd = 1.f / dtw;
            float rwd = rw * dtw;
            float ni[3];
            #pragma unroll
            for (int r = 0; r < 3; r++) ni[r] = g_node[b][i][kk[r]];
            float marg = sqrtf((maxa - mina + 15.f) * (1.f / BARRIERc));
            float inv95wp = __fdividef(95.0f, wp);
            bool degen = !(wp > 0.f);
            float bnew[3];
            #pragma unroll
            for (int r = 0; r < 3; r++) {
                float tj = lbj + wj * fr[r];
                float A = tj - marg * dtw;
                float Bv = tj + (gub + marg) * dtw;
                int klo = max(0, (int)ceilf((A - lbp) * inv95wp));
                int khi = min(Kd - 1, (int)floorf((Bv - lbp) * inv95wp));
                if (degen) { klo = 0; khi = Kd - 1; }
                if (khi < klo) { int cc = min(Kd - 1, max(0, klo)); klo = max(0, cc - 1); khi = min(Kd - 1, cc + 1); }
                float mval = 3.402823466e38f, ssum = 0.f;
                for (int kq = klo; kq <= khi; kq++) {
                    float tnk = lbp + wp * s_frac[kq];
                    float slope = (tnk - tj) * invd;
                    float e = edge_fn(slope, gub, rwd);
                    float x = s_a[cur][kq] + e;
                    float dlt = x - mval;
                    float tt = exp2f(-fabsf(dlt) * IG2);
                    if (dlt < 0.f) { ssum = fmaf(ssum, tt, 1.f); mval = x; }
                    else           { ssum += tt; }
                }
                bnew[r] = mval - GLN2 * __log2f(ssum);
            }
            float cn[3];
            #pragma unroll
            for (int r = 0; r < 3; r++) {
                g_beta[b][i][kk[r]] = bnew[r];
                cn[r] = ni[r] + bnew[r];
            }
            float l = fminf(fminf(cn[0], cn[1]), cn[2]);
            float h = fmaxf(fmaxf(cn[0], cn[1]), cn[2]);
            mina = o2f(__reduce_min_sync(0xffffffffu, f2o(l)));
            maxa = o2f(__reduce_max_sync(0xffffffffu, f2o(h)));
            #pragma unroll
            for (int r = 0; r < 3; r++) s_a[cur ^ 1][kk[r]] = cn[r];
            __syncwarp();
            cur ^= 1;
            lbp = lbj; wp = wj; twp = twj;
        }
    }
}

// ---------------- kernel 4: softmax over k, expectation of tau ----------------
__global__ void k4_out(const float* __restrict__ glb_lb, const float* __restrict__ glb_ub,
                       float* __restrict__ out) {
    int m = blockIdx.x, b = blockIdx.y, lane = threadIdx.x;  // 32 threads
    float T2 = g_T2[b];
    float lb = glb_lb[b * Mw + m] * T2;
    float ub = glb_ub[b * Mw + m] * T2;
    float w = ub - lb;
    float v[3], ta[3];
    #pragma unroll
    for (int r = 0; r < 3; r++) {
        int k = lane + 32 * r;
        v[r] = g_alpha[b][m][k] + g_beta[b][m][k];
        ta[r] = lb + w * ((float)k / 95.0f);
    }
    float l = fminf(fminf(v[0], v[1]), v[2]);
    float vmin = o2f(__reduce_min_sync(0xffffffffu, f2o(l)));
    float ps = 0.f, pts = 0.f;
    #pragma unroll
    for (int r = 0; r < 3; r++) {
        float p = exp2f((vmin - v[r]) * IG2);
        ps += p;
        pts = fmaf(p, ta[r], pts);
    }
    for (int o = 16; o; o >>= 1) {
        ps += __shfl_xor_sync(0xffffffffu, ps, o);
        pts += __shfl_xor_sync(0xffffffffu, pts, o);
    }
    if (lane == 0) out[b * Mw + m] = pts / ps;
}

extern "C" void kernel_launch(void* const* d_in, const int* in_sizes, int n_in,
                              void* d_out, int out_size) {
    const float* s1f    = (const float*)d_in[0];
    const float* s2f    = (const float*)d_in[1];
    const float* regw   = (const float*)d_in[2];
    const float* glb_lb = (const float*)d_in[3];
    const float* glb_ub = (const float*)d_in[4];
    const float* lgu    = (const float*)d_in[5];
    const float* t1     = (const float*)d_in[6];
    const float* t2     = (const float*)d_in[7];
    const float* twf    = (const float*)d_in[8];
    float* out = (float*)d_out;

    k0_maxes<<<Bn, 256>>>(t1, t2);
    k1_prep<<<dim3(Mw, Bn), Dd>>>(s1f, twf);
    k2_node<<<dim3(Kd / 8, Bn), 256>>>(s2f, glb_lb, glb_ub, twf);
    k3_scan<<<dim3(2, Bn), 32>>>(twf, regw, lgu, glb_lb, glb_ub);
    k4_out<<<dim3(Mw, Bn), 32>>>(glb_lb, glb_ub, out);
}

// round 3
// speedup vs baseline: 2.0579x; 1.3341x over previous
#include <cuda_runtime.h>
#include <math.h>

#define Bn 32
#define N1 512
#define N2 512
#define Dd 128
#define Mw 256
#define Kd 96
#define BARRIERc 10000.0f

#define IG2 14.4269504088896f   /* log2(e)/gamma */
#define GLN2 0.069314718055995f /* gamma*ln(2)   */
#define INFf __int_as_float(0x7f800000)

__device__ float g_T1[Bn], g_T2[Bn];
__device__ float g_s1at[Bn][Mw][Dd];
__device__ float g_node[Bn][Mw][Kd];
__device__ float g_alpha[Bn][Mw][Kd];
__device__ float g_beta[Bn][Mw][Kd];

// fast MUFU intrinsics (single-instruction approx versions)
__device__ __forceinline__ float ex2a(float x) { float y; asm("ex2.approx.f32 %0, %1;" : "=f"(y) : "f"(x)); return y; }
__device__ __forceinline__ float lg2a(float x) { float y; asm("lg2.approx.f32 %0, %1;" : "=f"(y) : "f"(x)); return y; }
__device__ __forceinline__ float sqrta(float x) { float y; asm("sqrt.approx.f32 %0, %1;" : "=f"(y) : "f"(x)); return y; }

// monotone float <-> orderable-uint mapping (for REDUX min/max on floats)
__device__ __forceinline__ unsigned f2o(float x) {
    unsigned u = __float_as_uint(x);
    return (u & 0x80000000u) ? ~u : (u | 0x80000000u);
}
__device__ __forceinline__ float o2f(unsigned v) {
    return __uint_as_float((v & 0x80000000u) ? (v ^ 0x80000000u) : ~v);
}

// ---------------- kernel 0: per-batch maxima of time vectors ----------------
__global__ void k0_maxes(const float* __restrict__ t1, const float* __restrict__ t2) {
    int b = blockIdx.x, t = threadIdx.x;  // 256 threads
    float m1 = -3.4e38f, m2 = -3.4e38f;
    for (int i = t; i < N1; i += 256) m1 = fmaxf(m1, t1[b * N1 + i]);
    for (int i = t; i < N2; i += 256) m2 = fmaxf(m2, t2[b * N2 + i]);
    __shared__ float s1[8], s2[8];
    for (int o = 16; o; o >>= 1) {
        m1 = fmaxf(m1, __shfl_xor_sync(0xffffffffu, m1, o));
        m2 = fmaxf(m2, __shfl_xor_sync(0xffffffffu, m2, o));
    }
    if ((t & 31) == 0) { s1[t >> 5] = m1; s2[t >> 5] = m2; }
    __syncthreads();
    if (t == 0) {
        float a = s1[0], c = s2[0];
        for (int w = 1; w < 8; w++) { a = fmaxf(a, s1[w]); c = fmaxf(c, s2[w]); }
        g_T1[b] = a; g_T2[b] = c;
    }
}

// ---------------- kernel 1: s1 interpolation at warp times ----------------
__global__ void k1_prep(const float* __restrict__ s1f, const float* __restrict__ tw) {
    int m = blockIdx.x, b = blockIdx.y, t = threadIdx.x;  // 128 threads
    float T1 = g_T1[b];
    float pos = tw[b * Mw + m] / T1;
    float x = fminf(fmaxf(pos, 0.f), 1.f) * (float)(N1 - 1);
    int i0 = min(max((int)x, 0), N1 - 2);
    float w = x - (float)i0;
    const float* r0 = s1f + ((size_t)b * N1 + i0) * Dd;
    float f0 = r0[t], f1 = r0[Dd + t];
    g_s1at[b][m][t] = f0 * (1.f - w) + f1 * w;
}

// ---------------- kernel 2: node costs (warp-per-k, 4-m ILP batch) ----------------
__global__ void k2_node(const float* __restrict__ s2f, const float* __restrict__ glb_lb,
                        const float* __restrict__ glb_ub, const float* __restrict__ tw) {
    int b = blockIdx.y;
    int wq = threadIdx.x >> 5, lane = threadIdx.x & 31;
    int k = blockIdx.x * 8 + wq;
    __shared__ float s_lb[Mw], s_w[Mw], s_tw[Mw];
    float T2 = g_T2[b];
    for (int i = threadIdx.x; i < Mw; i += 256) {
        float lb = glb_lb[b * Mw + i] * T2;
        float ub = glb_ub[b * Mw + i] * T2;
        s_lb[i] = lb; s_w[i] = ub - lb; s_tw[i] = tw[b * Mw + i];
    }
    __syncthreads();
    float frk = (float)k / 95.0f;
    float invT2 = 1.f / T2;
    const float* s2b = s2f + (size_t)b * N2 * Dd;
    int i0p = -1;
    float4 f0v = make_float4(0.f, 0.f, 0.f, 0.f), f1v = f0v;
    for (int m0 = 0; m0 < Mw; m0 += 4) {
        float acc[4], tks[4];
        #pragma unroll
        for (int u = 0; u < 4; u++) {
            int m = m0 + u;
            float tk = s_lb[m] + s_w[m] * frk;
            tks[u] = tk;
            float x = fminf(fmaxf(tk * invT2, 0.f), 1.f) * (float)(N2 - 1);
            int i0 = min(max((int)x, 0), N2 - 2);
            float w = x - (float)i0;
            if (i0 != i0p) {
                f0v = *((const float4*)(s2b + (size_t)i0 * Dd) + lane);
                f1v = *((const float4*)(s2b + (size_t)(i0 + 1) * Dd) + lane);
                i0p = i0;
            }
            float4 s1v = *((const float4*)(&g_s1at[b][m][0]) + lane);
            float d0 = s1v.x - (f0v.x + w * (f1v.x - f0v.x));
            float d1 = s1v.y - (f0v.y + w * (f1v.y - f0v.y));
            float d2 = s1v.z - (f0v.z + w * (f1v.z - f0v.z));
            float d3 = s1v.w - (f0v.w + w * (f1v.w - f0v.w));
            acc[u] = fmaf(d0, d0, fmaf(d1, d1, fmaf(d2, d2, d3 * d3)));
        }
        for (int o = 16; o; o >>= 1) {
            #pragma unroll
            for (int u = 0; u < 4; u++)
                acc[u] += __shfl_xor_sync(0xffffffffu, acc[u], o);
        }
        if (lane == 0) {
            #pragma unroll
            for (int u = 0; u < 4; u++) {
                int m = m0 + u;
                float twm = s_tw[m];
                float wt = 0.f;
                if (m > 0) wt += twm - s_tw[m - 1];
                if (m < Mw - 1) wt += s_tw[m + 1] - twm;
                wt *= 0.5f;
                float node = acc[u] * wt;
                float tk = tks[u];
                if (m == 0) node += BARRIERc * tk * tk;
                if (m == Mw - 1) { float dd = tk - T2; node += BARRIERc * dd * dd; }
                g_node[b][m][k] = node;
            }
        }
    }
}

// ---------------- edge cost ----------------
__device__ __forceinline__ float edge_fn(float slope, float gub, float rwd) {
    float d1 = slope - 1.f;
    float n1 = fminf(slope, 0.f);
    float r2 = fmaxf(slope - gub, 0.f);
    float pen = fmaf(n1, n1, r2 * r2);
    return fmaf(BARRIERc, pen, rwd * d1 * d1);
}

// windowed softmin over s_a[jlo..jhi] vs candidate times on prev grid
// fast path: <=4 entries, branch-free (invalid -> +INF -> ex2(-inf)=0)
__device__ __forceinline__ float softmin_win(
    const float* __restrict__ sa, const float* __restrict__ sfrac,
    int jlo, int jhi, float tref, float sgn, float invd,
    float lbp, float wp, float gub, float rwd) {
    if (jhi - jlo < 4) {
        float x[4];
        #pragma unroll
        for (int u = 0; u < 4; u++) {
            int j = jlo + u;
            int jc = min(j, Kd - 1);
            float tpj = lbp + wp * sfrac[jc];
            float slope = sgn * (tref - tpj) * invd;
            float e = edge_fn(slope, gub, rwd);
            float xv = sa[jc] + e;
            x[u] = (j <= jhi) ? xv : INFf;
        }
        float mv = fminf(fminf(x[0], x[1]), fminf(x[2], x[3]));
        float ss = ex2a((mv - x[0]) * IG2) + ex2a((mv - x[1]) * IG2)
                 + ex2a((mv - x[2]) * IG2) + ex2a((mv - x[3]) * IG2);
        return mv - GLN2 * lg2a(ss);
    }
    float mval = INFf, ssum = 0.f;
    for (int j = jlo; j <= jhi; j++) {
        float tpj = lbp + wp * sfrac[j];
        float slope = sgn * (tref - tpj) * invd;
        float e = edge_fn(slope, gub, rwd);
        float xv = sa[j] + e;
        float dlt = xv - mval;
        float tt = ex2a(-fabsf(dlt) * IG2);
        if (dlt < 0.f) { ssum = fmaf(ssum, tt, 1.f); mval = xv; }
        else           { ssum += tt; }
    }
    return mval - GLN2 * lg2a(ssum);
}

// ---------------- kernel 3: single-warp windowed soft-min scans ----------------
__global__ void k3_scan(const float* __restrict__ tw, const float* __restrict__ reg_wt,
                        const float* __restrict__ lgu, const float* __restrict__ glb_lb,
                        const float* __restrict__ glb_ub) {
    int dir = blockIdx.x, b = blockIdx.y;
    int lane = threadIdx.x;  // 32 threads = 1 warp
    __shared__ float s_lb[Mw], s_w[Mw], s_tw[Mw], s_frac[Kd], s_a[2][Kd];
    float T2 = g_T2[b];
    for (int i = lane; i < Mw; i += 32) {
        float lb = glb_lb[b * Mw + i] * T2;
        float ub = glb_ub[b * Mw + i] * T2;
        s_lb[i] = lb; s_w[i] = ub - lb; s_tw[i] = tw[b * Mw + i];
    }
    for (int i = lane; i < Kd; i += 32) s_frac[i] = (float)i / 95.0f;
    __syncwarp();
    float rw = reg_wt[b], gub = lgu[b];
    int kk[3]; float fr[3];
    #pragma unroll
    for (int r = 0; r < 3; r++) { kk[r] = lane + 32 * r; fr[r] = s_frac[kk[r]]; }

    if (dir == 0) {
        float a[3], nn[3];
        #pragma unroll
        for (int r = 0; r < 3; r++) {
            a[r] = g_node[b][0][kk[r]];
            g_alpha[b][0][kk[r]] = a[r];
            s_a[0][kk[r]] = a[r];
        }
        float l3 = fminf(fminf(a[0], a[1]), a[2]);
        float h3 = fmaxf(fmaxf(a[0], a[1]), a[2]);
        float mina = o2f(__reduce_min_sync(0xffffffffu, f2o(l3)));
        float maxa = o2f(__reduce_max_sync(0xffffffffu, f2o(h3)));
        #pragma unroll
        for (int r = 0; r < 3; r++) nn[r] = g_node[b][1][kk[r]];
        __syncwarp();
        int cur = 0;
        float lbp = s_lb[0], wp = s_w[0], twp = s_tw[0];
        for (int i = 0; i < Mw - 1; i++) {
            float lbn = s_lb[i + 1], wn = s_w[i + 1], twn = s_tw[i + 1];
            float dtw = twn - twp;
            float invd = __fdividef(1.f, dtw);
            float rwd = rw * dtw;
            float nn2[3];
            if (i + 2 < Mw) {
                #pragma unroll
                for (int r = 0; r < 3; r++) nn2[r] = g_node[b][i + 2][kk[r]];
            }
            float marg = sqrta((maxa - mina + 15.f) * (1.f / BARRIERc));
            float inv95wp = __fdividef(95.0f, wp);
            bool degen = !(wp > 0.f);
            float loOff = (gub + marg) * dtw;   // below tnk
            float hiOff = marg * dtw;           // above tnk
            float anew[3];
            #pragma unroll
            for (int r = 0; r < 3; r++) {
                float tnk = lbn + wn * fr[r];
                int jlo = max(0, __float2int_ru((tnk - loOff - lbp) * inv95wp));
                int jhi = min(Kd - 1, __float2int_rd((tnk + hiOff - lbp) * inv95wp));
                if (degen) { jlo = 0; jhi = Kd - 1; }
                if (jhi < jlo) { int c = min(Kd - 1, max(0, jlo)); jlo = max(0, c - 1); jhi = min(Kd - 1, c + 1); }
                float sm = softmin_win(s_a[cur], s_frac, jlo, jhi, tnk, 1.f, invd, lbp, wp, gub, rwd);
                anew[r] = nn[r] + sm;
            }
            float l = fminf(fminf(anew[0], anew[1]), anew[2]);
            float h = fmaxf(fmaxf(anew[0], anew[1]), anew[2]);
            mina = o2f(__reduce_min_sync(0xffffffffu, f2o(l)));
            maxa = o2f(__reduce_max_sync(0xffffffffu, f2o(h)));
            #pragma unroll
            for (int r = 0; r < 3; r++) {
                s_a[cur ^ 1][kk[r]] = anew[r];
                g_alpha[b][i + 1][kk[r]] = anew[r];
                nn[r] = nn2[r];
            }
            __syncwarp();
            cur ^= 1;
            lbp = lbn; wp = wn; twp = twn;
        }
    } else {
        float c[3];
        #pragma unroll
        for (int r = 0; r < 3; r++) {
            g_beta[b][Mw - 1][kk[r]] = 0.f;
            c[r] = g_node[b][Mw - 1][kk[r]];
            s_a[0][kk[r]] = c[r];
        }
        float l3 = fminf(fminf(c[0], c[1]), c[2]);
        float h3 = fmaxf(fmaxf(c[0], c[1]), c[2]);
        float mina = o2f(__reduce_min_sync(0xffffffffu, f2o(l3)));
        float maxa = o2f(__reduce_max_sync(0xffffffffu, f2o(h3)));
        __syncwarp();
        int cur = 0;
        float lbp = s_lb[Mw - 1], wp = s_w[Mw - 1], twp = s_tw[Mw - 1];
        for (int i = Mw - 2; i >= 0; i--) {
            float lbj = s_lb[i], wj = s_w[i], twj = s_tw[i];
            float dtw = twp - twj;
            float invd = __fdividef(1.f, dtw);
            float rwd = rw * dtw;
            float ni[3];
            #pragma unroll
            for (int r = 0; r < 3; r++) ni[r] = g_node[b][i][kk[r]];
            float marg = sqrta((maxa - mina + 15.f) * (1.f / BARRIERc));
            float inv95wp = __fdividef(95.0f, wp);
            bool degen = !(wp > 0.f);
            float loOff = marg * dtw;           // below tj
            float hiOff = (gub + marg) * dtw;   // above tj
            float bnew[3];
            #pragma unroll
            for (int r = 0; r < 3; r++) {
                float tj = lbj + wj * fr[r];
                int klo = max(0, __float2int_ru((tj - loOff - lbp) * inv95wp));
                int khi = min(Kd - 1, __float2int_rd((tj + hiOff - lbp) * inv95wp));
                if (degen) { klo = 0; khi = Kd - 1; }
                if (khi < klo) { int cc = min(Kd - 1, max(0, klo)); klo = max(0, cc - 1); khi = min(Kd - 1, cc + 1); }
                bnew[r] = softmin_win(s_a[cur], s_frac, klo, khi, tj, -1.f, invd, lbp, wp, gub, rwd);
            }
            float cn[3];
            #pragma unroll
            for (int r = 0; r < 3; r++) {
                g_beta[b][i][kk[r]] = bnew[r];
                cn[r] = ni[r] + bnew[r];
            }
            float l = fminf(fminf(cn[0], cn[1]), cn[2]);
            float h = fmaxf(fmaxf(cn[0], cn[1]), cn[2]);
            mina = o2f(__reduce_min_sync(0xffffffffu, f2o(l)));
            maxa = o2f(__reduce_max_sync(0xffffffffu, f2o(h)));
            #pragma unroll
            for (int r = 0; r < 3; r++) s_a[cur ^ 1][kk[r]] = cn[r];
            __syncwarp();
            cur ^= 1;
            lbp = lbj; wp = wj; twp = twj;
        }
    }
}

// ---------------- kernel 4: softmax over k, expectation of tau ----------------
__global__ void k4_out(const float* __restrict__ glb_lb, const float* __restrict__ glb_ub,
                       float* __restrict__ out) {
    int m = blockIdx.x, b = blockIdx.y, lane = threadIdx.x;  // 32 threads
    float T2 = g_T2[b];
    float lb = glb_lb[b * Mw + m] * T2;
    float ub = glb_ub[b * Mw + m] * T2;
    float w = ub - lb;
    float v[3], ta[3];
    #pragma unroll
    for (int r = 0; r < 3; r++) {
        int k = lane + 32 * r;
        v[r] = g_alpha[b][m][k] + g_beta[b][m][k];
        ta[r] = lb + w * ((float)k / 95.0f);
    }
    float l = fminf(fminf(v[0], v[1]), v[2]);
    float vmin = o2f(__reduce_min_sync(0xffffffffu, f2o(l)));
    float ps = 0.f, pts = 0.f;
    #pragma unroll
    for (int r = 0; r < 3; r++) {
        float p = ex2a((vmin - v[r]) * IG2);
        ps += p;
        pts = fmaf(p, ta[r], pts);
    }
    for (int o = 16; o; o >>= 1) {
        ps += __shfl_xor_sync(0xffffffffu, ps, o);
        pts += __shfl_xor_sync(0xffffffffu, pts, o);
    }
    if (lane == 0) out[b * Mw + m] = pts / ps;
}

extern "C" void kernel_launch(void* const* d_in, const int* in_sizes, int n_in,
                              void* d_out, int out_size) {
    const float* s1f    = (const float*)d_in[0];
    const float* s2f    = (const float*)d_in[1];
    const float* regw   = (const float*)d_in[2];
    const float* glb_lb = (const float*)d_in[3];
    const float* glb_ub = (const float*)d_in[4];
    const float* lgu    = (const float*)d_in[5];
    const float* t1     = (const float*)d_in[6];
    const float* t2     = (const float*)d_in[7];
    const float* twf    = (const float*)d_in[8];
    float* out = (float*)d_out;

    k0_maxes<<<Bn, 256>>>(t1, t2);
    k1_prep<<<dim3(Mw, Bn), Dd>>>(s1f, twf);
    k2_node<<<dim3(Kd / 8, Bn), 256>>>(s2f, glb_lb, glb_ub, twf);
    k3_scan<<<dim3(2, Bn), 32>>>(twf, regw, lgu, glb_lb, glb_ub);
    k4_out<<<dim3(Mw, Bn), 32>>>(glb_lb, glb_ub, out);
}

// round 4
// speedup vs baseline: 2.7210x; 1.3222x over previous
#include <cuda_runtime.h>
#include <math.h>

#define Bn 32
#define N1 512
#define N2 512
#define Dd 128
#define Mw 256
#define Kd 96
#define BARRIERc 10000.0f

#define IG2 14.4269504088896f   /* log2(e)/gamma */
#define GLN2 0.069314718055995f /* gamma*ln(2)   */
#define INFf __int_as_float(0x7f800000)

__device__ float g_T1[Bn], g_T2[Bn];
__device__ float g_s1at[Bn][Mw][Dd];
__device__ float g_node[Bn][Mw][Kd];
__device__ float g_alpha[Bn][Mw][Kd];
__device__ float g_beta[Bn][Mw][Kd];

// fast MUFU intrinsics
__device__ __forceinline__ float ex2a(float x) { float y; asm("ex2.approx.f32 %0, %1;" : "=f"(y) : "f"(x)); return y; }
__device__ __forceinline__ float lg2a(float x) { float y; asm("lg2.approx.f32 %0, %1;" : "=f"(y) : "f"(x)); return y; }
__device__ __forceinline__ float sqrta(float x) { float y; asm("sqrt.approx.f32 %0, %1;" : "=f"(y) : "f"(x)); return y; }

// monotone float <-> orderable-uint mapping (REDUX min/max on floats)
__device__ __forceinline__ unsigned f2o(float x) {
    unsigned u = __float_as_uint(x);
    return (u & 0x80000000u) ? ~u : (u | 0x80000000u);
}
__device__ __forceinline__ float o2f(unsigned v) {
    return __uint_as_float((v & 0x80000000u) ? (v ^ 0x80000000u) : ~v);
}

// ---------------- kernel 0 ----------------
__global__ void k0_maxes(const float* __restrict__ t1, const float* __restrict__ t2) {
    int b = blockIdx.x, t = threadIdx.x;
    float m1 = -3.4e38f, m2 = -3.4e38f;
    for (int i = t; i < N1; i += 256) m1 = fmaxf(m1, t1[b * N1 + i]);
    for (int i = t; i < N2; i += 256) m2 = fmaxf(m2, t2[b * N2 + i]);
    __shared__ float s1[8], s2[8];
    for (int o = 16; o; o >>= 1) {
        m1 = fmaxf(m1, __shfl_xor_sync(0xffffffffu, m1, o));
        m2 = fmaxf(m2, __shfl_xor_sync(0xffffffffu, m2, o));
    }
    if ((t & 31) == 0) { s1[t >> 5] = m1; s2[t >> 5] = m2; }
    __syncthreads();
    if (t == 0) {
        float a = s1[0], c = s2[0];
        for (int w = 1; w < 8; w++) { a = fmaxf(a, s1[w]); c = fmaxf(c, s2[w]); }
        g_T1[b] = a; g_T2[b] = c;
    }
}

// ---------------- kernel 1 ----------------
__global__ void k1_prep(const float* __restrict__ s1f, const float* __restrict__ tw) {
    int m = blockIdx.x, b = blockIdx.y, t = threadIdx.x;
    float T1 = g_T1[b];
    float pos = tw[b * Mw + m] / T1;
    float x = fminf(fmaxf(pos, 0.f), 1.f) * (float)(N1 - 1);
    int i0 = min(max((int)x, 0), N1 - 2);
    float w = x - (float)i0;
    const float* r0 = s1f + ((size_t)b * N1 + i0) * Dd;
    float f0 = r0[t], f1 = r0[Dd + t];
    g_s1at[b][m][t] = f0 * (1.f - w) + f1 * w;
}

// ---------------- kernel 2 ----------------
__global__ void k2_node(const float* __restrict__ s2f, const float* __restrict__ glb_lb,
                        const float* __restrict__ glb_ub, const float* __restrict__ tw) {
    int b = blockIdx.y;
    int wq = threadIdx.x >> 5, lane = threadIdx.x & 31;
    int k = blockIdx.x * 8 + wq;
    __shared__ float s_lb[Mw], s_w[Mw], s_tw[Mw];
    float T2 = g_T2[b];
    for (int i = threadIdx.x; i < Mw; i += 256) {
        float lb = glb_lb[b * Mw + i] * T2;
        float ub = glb_ub[b * Mw + i] * T2;
        s_lb[i] = lb; s_w[i] = ub - lb; s_tw[i] = tw[b * Mw + i];
    }
    __syncthreads();
    float frk = (float)k / 95.0f;
    float invT2 = 1.f / T2;
    const float* s2b = s2f + (size_t)b * N2 * Dd;
    int i0p = -1;
    float4 f0v = make_float4(0.f, 0.f, 0.f, 0.f), f1v = f0v;
    for (int m0 = 0; m0 < Mw; m0 += 4) {
        float acc[4], tks[4];
        #pragma unroll
        for (int u = 0; u < 4; u++) {
            int m = m0 + u;
            float tk = s_lb[m] + s_w[m] * frk;
            tks[u] = tk;
            float x = fminf(fmaxf(tk * invT2, 0.f), 1.f) * (float)(N2 - 1);
            int i0 = min(max((int)x, 0), N2 - 2);
            float w = x - (float)i0;
            if (i0 != i0p) {
                f0v = *((const float4*)(s2b + (size_t)i0 * Dd) + lane);
                f1v = *((const float4*)(s2b + (size_t)(i0 + 1) * Dd) + lane);
                i0p = i0;
            }
            float4 s1v = *((const float4*)(&g_s1at[b][m][0]) + lane);
            float d0 = s1v.x - (f0v.x + w * (f1v.x - f0v.x));
            float d1 = s1v.y - (f0v.y + w * (f1v.y - f0v.y));
            float d2 = s1v.z - (f0v.z + w * (f1v.z - f0v.z));
            float d3 = s1v.w - (f0v.w + w * (f1v.w - f0v.w));
            acc[u] = fmaf(d0, d0, fmaf(d1, d1, fmaf(d2, d2, d3 * d3)));
        }
        for (int o = 16; o; o >>= 1) {
            #pragma unroll
            for (int u = 0; u < 4; u++)
                acc[u] += __shfl_xor_sync(0xffffffffu, acc[u], o);
        }
        if (lane == 0) {
            #pragma unroll
            for (int u = 0; u < 4; u++) {
                int m = m0 + u;
                float twm = s_tw[m];
                float wt = 0.f;
                if (m > 0) wt += twm - s_tw[m - 1];
                if (m < Mw - 1) wt += s_tw[m + 1] - twm;
                wt *= 0.5f;
                float node = acc[u] * wt;
                float tk = tks[u];
                if (m == 0) node += BARRIERc * tk * tk;
                if (m == Mw - 1) { float dd = tk - T2; node += BARRIERc * dd * dd; }
                g_node[b][m][k] = node;
            }
        }
    }
}

// ---------------- edge cost ----------------
__device__ __forceinline__ float edge_fn(float slope, float gub, float rwd) {
    float d1 = slope - 1.f;
    float n1 = fminf(slope, 0.f);
    float r2 = fmaxf(slope - gub, 0.f);
    float pen = fmaf(n1, n1, r2 * r2);
    return fmaf(BARRIERc, pen, rwd * d1 * d1);
}

// general windowed softmin (fallback path)
__device__ __forceinline__ float softmin_win(
    const float* __restrict__ sa, const float* __restrict__ sfrac,
    int jlo, int jhi, float tref, float sgn, float invd,
    float lbp, float wp, float gub, float rwd) {
    if (jhi - jlo < 4) {
        float x[4];
        #pragma unroll
        for (int u = 0; u < 4; u++) {
            int j = jlo + u;
            int jc = min(j, Kd - 1);
            float tpj = lbp + wp * sfrac[jc];
            float slope = sgn * (tref - tpj) * invd;
            float e = edge_fn(slope, gub, rwd);
            float xv = sa[jc] + e;
            x[u] = (j <= jhi) ? xv : INFf;
        }
        float mv = fminf(fminf(x[0], x[1]), fminf(x[2], x[3]));
        float ss = ex2a((mv - x[0]) * IG2) + ex2a((mv - x[1]) * IG2)
                 + ex2a((mv - x[2]) * IG2) + ex2a((mv - x[3]) * IG2);
        return mv - GLN2 * lg2a(ss);
    }
    float mval = INFf, ssum = 0.f;
    for (int j = jlo; j <= jhi; j++) {
        float tpj = lbp + wp * sfrac[j];
        float slope = sgn * (tref - tpj) * invd;
        float e = edge_fn(slope, gub, rwd);
        float xv = sa[j] + e;
        float dlt = xv - mval;
        float tt = ex2a(-fabsf(dlt) * IG2);
        if (dlt < 0.f) { ssum = fmaf(ssum, tt, 1.f); mval = xv; }
        else           { ssum += tt; }
    }
    return mval - GLN2 * lg2a(ssum);
}

// ---------------- kernel 3: single-warp scans, delta-table fast path ----------------
__global__ void k3_scan(const float* __restrict__ tw, const float* __restrict__ reg_wt,
                        const float* __restrict__ lgu, const float* __restrict__ glb_lb,
                        const float* __restrict__ glb_ub) {
    int dir = blockIdx.x, b = blockIdx.y;
    int lane = threadIdx.x;  // 32 threads = 1 warp
    __shared__ float s_lb[Mw], s_w[Mw], s_tw[Mw], s_frac[Kd], s_a[2][Kd];
    float T2 = g_T2[b];
    for (int i = lane; i < Mw; i += 32) {
        float lb = glb_lb[b * Mw + i] * T2;
        float ub = glb_ub[b * Mw + i] * T2;
        s_lb[i] = lb; s_w[i] = ub - lb; s_tw[i] = tw[b * Mw + i];
    }
    for (int i = lane; i < Kd; i += 32) s_frac[i] = (float)i / 95.0f;
    __syncwarp();
    float rw = reg_wt[b], gub = lgu[b];
    int kk[3]; float fr[3];
    #pragma unroll
    for (int r = 0; r < 3; r++) { kk[r] = lane + 32 * r; fr[r] = s_frac[kk[r]]; }

    if (dir == 0) {
        float a[3], nn[3];
        #pragma unroll
        for (int r = 0; r < 3; r++) {
            a[r] = g_node[b][0][kk[r]];
            g_alpha[b][0][kk[r]] = a[r];
            s_a[0][kk[r]] = a[r];
        }
        float l3 = fminf(fminf(a[0], a[1]), a[2]);
        float h3 = fmaxf(fmaxf(a[0], a[1]), a[2]);
        float mina = o2f(__reduce_min_sync(0xffffffffu, f2o(l3)));
        float maxa = o2f(__reduce_max_sync(0xffffffffu, f2o(h3)));
        #pragma unroll
        for (int r = 0; r < 3; r++) nn[r] = g_node[b][1][kk[r]];
        __syncwarp();
        int cur = 0;
        float lbp = s_lb[0], wp = s_w[0], twp = s_tw[0];
        for (int i = 0; i < Mw - 1; i++) {
            float lbn = s_lb[i + 1], wn = s_w[i + 1], twn = s_tw[i + 1];
            float dtw = twn - twp;
            float invd = __fdividef(1.f, dtw);
            float rwd = rw * dtw;
            float nn2[3];
            if (i + 2 < Mw) {
                #pragma unroll
                for (int r = 0; r < 3; r++) nn2[r] = g_node[b][i + 2][kk[r]];
            }
            float marg = sqrta((maxa - mina + 15.f) * (1.f / BARRIERc));
            float anew[3];
            bool uni = (lbn == lbp) && (wn == wp) && (wp > 0.f);
            bool fast = false;
            int d0 = 0, dmax = 0;
            float e[4];
            if (uni) {
                float u95 = 95.0f * dtw * __fdividef(1.f, wp);   // δ per time unit
                d0 = -__float2int_rd(marg * u95);
                dmax = __float2int_rd((gub + marg) * u95);
                if (dmax - d0 < 4) {
                    fast = true;
                    float sinv = __fdividef(wp, 95.0f * dtw);    // slope per δ
                    #pragma unroll
                    for (int t = 0; t < 4; t++) {
                        float sl = (float)(d0 + t) * sinv;
                        e[t] = (d0 + t <= dmax) ? edge_fn(sl, gub, rwd) : INFf;
                    }
                }
            }
            if (fast) {
                #pragma unroll
                for (int r = 0; r < 3; r++) {
                    int jb = kk[r] - d0;
                    float x[4];
                    #pragma unroll
                    for (int t = 0; t < 4; t++) {
                        int j = jb - t;
                        int jc = min(max(j, 0), Kd - 1);
                        float xv = s_a[cur][jc] + e[t];
                        x[t] = (j == jc) ? xv : INFf;
                    }
                    float mv = fminf(fminf(x[0], x[1]), fminf(x[2], x[3]));
                    float ss = ex2a((mv - x[0]) * IG2) + ex2a((mv - x[1]) * IG2)
                             + ex2a((mv - x[2]) * IG2) + ex2a((mv - x[3]) * IG2);
                    anew[r] = nn[r] + mv - GLN2 * lg2a(ss);
                }
            } else {
                float inv95wp = __fdividef(95.0f, wp);
                bool degen = !(wp > 0.f);
                float loOff = (gub + marg) * dtw;
                float hiOff = marg * dtw;
                #pragma unroll
                for (int r = 0; r < 3; r++) {
                    float tnk = lbn + wn * fr[r];
                    int jlo = max(0, __float2int_ru((tnk - loOff - lbp) * inv95wp));
                    int jhi = min(Kd - 1, __float2int_rd((tnk + hiOff - lbp) * inv95wp));
                    if (degen) { jlo = 0; jhi = Kd - 1; }
                    if (jhi < jlo) { int c = min(Kd - 1, max(0, jlo)); jlo = max(0, c - 1); jhi = min(Kd - 1, c + 1); }
                    float sm = softmin_win(s_a[cur], s_frac, jlo, jhi, tnk, 1.f, invd, lbp, wp, gub, rwd);
                    anew[r] = nn[r] + sm;
                }
            }
            float l = fminf(fminf(anew[0], anew[1]), anew[2]);
            float h = fmaxf(fmaxf(anew[0], anew[1]), anew[2]);
            mina = o2f(__reduce_min_sync(0xffffffffu, f2o(l)));
            maxa = o2f(__reduce_max_sync(0xffffffffu, f2o(h)));
            #pragma unroll
            for (int r = 0; r < 3; r++) {
                s_a[cur ^ 1][kk[r]] = anew[r];
                g_alpha[b][i + 1][kk[r]] = anew[r];
                nn[r] = nn2[r];
            }
            __syncwarp();
            cur ^= 1;
            lbp = lbn; wp = wn; twp = twn;
        }
    } else {
        float c[3];
        #pragma unroll
        for (int r = 0; r < 3; r++) {
            g_beta[b][Mw - 1][kk[r]] = 0.f;
            c[r] = g_node[b][Mw - 1][kk[r]];
            s_a[0][kk[r]] = c[r];
        }
        float l3 = fminf(fminf(c[0], c[1]), c[2]);
        float h3 = fmaxf(fmaxf(c[0], c[1]), c[2]);
        float mina = o2f(__reduce_min_sync(0xffffffffu, f2o(l3)));
        float maxa = o2f(__reduce_max_sync(0xffffffffu, f2o(h3)));
        __syncwarp();
        int cur = 0;
        float lbp = s_lb[Mw - 1], wp = s_w[Mw - 1], twp = s_tw[Mw - 1];
        for (int i = Mw - 2; i >= 0; i--) {
            float lbj = s_lb[i], wj = s_w[i], twj = s_tw[i];
            float dtw = twp - twj;
            float invd = __fdividef(1.f, dtw);
            float rwd = rw * dtw;
            float ni[3];
            #pragma unroll
            for (int r = 0; r < 3; r++) ni[r] = g_node[b][i][kk[r]];
            float marg = sqrta((maxa - mina + 15.f) * (1.f / BARRIERc));
            float bnew[3];
            bool uni = (lbj == lbp) && (wj == wp) && (wp > 0.f);
            bool fast = false;
            int d0 = 0, dmax = 0;
            float e[4];
            if (uni) {
                float u95 = 95.0f * dtw * __fdividef(1.f, wp);
                d0 = -__float2int_rd(marg * u95);
                dmax = __float2int_rd((gub + marg) * u95);
                if (dmax - d0 < 4) {
                    fast = true;
                    float sinv = __fdividef(wp, 95.0f * dtw);
                    #pragma unroll
                    for (int t = 0; t < 4; t++) {
                        float sl = (float)(d0 + t) * sinv;
                        e[t] = (d0 + t <= dmax) ? edge_fn(sl, gub, rwd) : INFf;
                    }
                }
            }
            if (fast) {
                #pragma unroll
                for (int r = 0; r < 3; r++) {
                    int kb = kk[r] + d0;
                    float x[4];
                    #pragma unroll
                    for (int t = 0; t < 4; t++) {
                        int kt = kb + t;
                        int kc = min(max(kt, 0), Kd - 1);
                        float xv = s_a[cur][kc] + e[t];
                        x[t] = (kt == kc) ? xv : INFf;
                    }
                    float mv = fminf(fminf(x[0], x[1]), fminf(x[2], x[3]));
                    float ss = ex2a((mv - x[0]) * IG2) + ex2a((mv - x[1]) * IG2)
                             + ex2a((mv - x[2]) * IG2) + ex2a((mv - x[3]) * IG2);
                    bnew[r] = mv - GLN2 * lg2a(ss);
                }
            } else {
                float inv95wp = __fdividef(95.0f, wp);
                bool degen = !(wp > 0.f);
                float loOff = marg * dtw;
                float hiOff = (gub + marg) * dtw;
                #pragma unroll
                for (int r = 0; r < 3; r++) {
                    float tj = lbj + wj * fr[r];
                    int klo = max(0, __float2int_ru((tj - loOff - lbp) * inv95wp));
                    int khi = min(Kd - 1, __float2int_rd((tj + hiOff - lbp) * inv95wp));
                    if (degen) { klo = 0; khi = Kd - 1; }
                    if (khi < klo) { int cc = min(Kd - 1, max(0, klo)); klo = max(0, cc - 1); khi = min(Kd - 1, cc + 1); }
                    bnew[r] = softmin_win(s_a[cur], s_frac, klo, khi, tj, -1.f, invd, lbp, wp, gub, rwd);
                }
            }
            float cn[3];
            #pragma unroll
            for (int r = 0; r < 3; r++) {
                g_beta[b][i][kk[r]] = bnew[r];
                cn[r] = ni[r] + bnew[r];
            }
            float l = fminf(fminf(cn[0], cn[1]), cn[2]);
            float h = fmaxf(fmaxf(cn[0], cn[1]), cn[2]);
            mina = o2f(__reduce_min_sync(0xffffffffu, f2o(l)));
            maxa = o2f(__reduce_max_sync(0xffffffffu, f2o(h)));
            #pragma unroll
            for (int r = 0; r < 3; r++) s_a[cur ^ 1][kk[r]] = cn[r];
            __syncwarp();
            cur ^= 1;
            lbp = lbj; wp = wj; twp = twj;
        }
    }
}

// ---------------- kernel 4 ----------------
__global__ void k4_out(const float* __restrict__ glb_lb, const float* __restrict__ glb_ub,
                       float* __restrict__ out) {
    int m = blockIdx.x, b = blockIdx.y, lane = threadIdx.x;
    float T2 = g_T2[b];
    float lb = glb_lb[b * Mw + m] * T2;
    float ub = glb_ub[b * Mw + m] * T2;
    float w = ub - lb;
    float v[3], ta[3];
    #pragma unroll
    for (int r = 0; r < 3; r++) {
        int k = lane + 32 * r;
        v[r] = g_alpha[b][m][k] + g_beta[b][m][k];
        ta[r] = lb + w * ((float)k / 95.0f);
    }
    float l = fminf(fminf(v[0], v[1]), v[2]);
    float vmin = o2f(__reduce_min_sync(0xffffffffu, f2o(l)));
    float ps = 0.f, pts = 0.f;
    #pragma unroll
    for (int r = 0; r < 3; r++) {
        float p = ex2a((vmin - v[r]) * IG2);
        ps += p;
        pts = fmaf(p, ta[r], pts);
    }
    for (int o = 16; o; o >>= 1) {
        ps += __shfl_xor_sync(0xffffffffu, ps, o);
        pts += __shfl_xor_sync(0xffffffffu, pts, o);
    }
    if (lane == 0) out[b * Mw + m] = pts / ps;
}

extern "C" void kernel_launch(void* const* d_in, const int* in_sizes, int n_in,
                              void* d_out, int out_size) {
    const float* s1f    = (const float*)d_in[0];
    const float* s2f    = (const float*)d_in[1];
    const float* regw   = (const float*)d_in[2];
    const float* glb_lb = (const float*)d_in[3];
    const float* glb_ub = (const float*)d_in[4];
    const float* lgu    = (const float*)d_in[5];
    const float* t1     = (const float*)d_in[6];
    const float* t2     = (const float*)d_in[7];
    const float* twf    = (const float*)d_in[8];
    float* out = (float*)d_out;

    k0_maxes<<<Bn, 256>>>(t1, t2);
    k1_prep<<<dim3(Mw, Bn), Dd>>>(s1f, twf);
    k2_node<<<dim3(Kd / 8, Bn), 256>>>(s2f, glb_lb, glb_ub, twf);
    k3_scan<<<dim3(2, Bn), 32>>>(twf, regw, lgu, glb_lb, glb_ub);
    k4_out<<<dim3(Mw, Bn), 32>>>(glb_lb, glb_ub, out);
}

// round 5
// speedup vs baseline: 3.3659x; 1.2370x over previous
#include <cuda_runtime.h>
#include <math.h>

#define Bn 32
#define N1 512
#define N2 512
#define Dd 128
#define Mw 256
#define Kd 96
#define BARRIERc 10000.0f

#define IG2 14.4269504088896f   /* log2(e)/gamma */
#define GLN2 0.069314718055995f /* gamma*ln(2)   */
#define INFf __int_as_float(0x7f800000)
#define FULLM 0xffffffffu

__device__ float g_T1[Bn], g_T2[Bn];
__device__ float g_s1at[Bn][Mw][Dd];
__device__ float g_node[Bn][Mw][Kd];
__device__ float g_alpha[Bn][Mw][Kd];
__device__ float g_beta[Bn][Mw][Kd];

// fast MUFU intrinsics
__device__ __forceinline__ float ex2a(float x) { float y; asm("ex2.approx.f32 %0, %1;" : "=f"(y) : "f"(x)); return y; }
__device__ __forceinline__ float lg2a(float x) { float y; asm("lg2.approx.f32 %0, %1;" : "=f"(y) : "f"(x)); return y; }
__device__ __forceinline__ float sqrta(float x) { float y; asm("sqrt.approx.f32 %0, %1;" : "=f"(y) : "f"(x)); return y; }

// monotone float <-> orderable-uint mapping (REDUX min/max on floats)
__device__ __forceinline__ unsigned f2o(float x) {
    unsigned u = __float_as_uint(x);
    return (u & 0x80000000u) ? ~u : (u | 0x80000000u);
}
__device__ __forceinline__ float o2f(unsigned v) {
    return __uint_as_float((v & 0x80000000u) ? (v ^ 0x80000000u) : ~v);
}

// ---------------- kernel 0 ----------------
__global__ void k0_maxes(const float* __restrict__ t1, const float* __restrict__ t2) {
    int b = blockIdx.x, t = threadIdx.x;
    float m1 = -3.4e38f, m2 = -3.4e38f;
    for (int i = t; i < N1; i += 256) m1 = fmaxf(m1, t1[b * N1 + i]);
    for (int i = t; i < N2; i += 256) m2 = fmaxf(m2, t2[b * N2 + i]);
    __shared__ float s1[8], s2[8];
    for (int o = 16; o; o >>= 1) {
        m1 = fmaxf(m1, __shfl_xor_sync(FULLM, m1, o));
        m2 = fmaxf(m2, __shfl_xor_sync(FULLM, m2, o));
    }
    if ((t & 31) == 0) { s1[t >> 5] = m1; s2[t >> 5] = m2; }
    __syncthreads();
    if (t == 0) {
        float a = s1[0], c = s2[0];
        for (int w = 1; w < 8; w++) { a = fmaxf(a, s1[w]); c = fmaxf(c, s2[w]); }
        g_T1[b] = a; g_T2[b] = c;
    }
}

// ---------------- kernel 1 ----------------
__global__ void k1_prep(const float* __restrict__ s1f, const float* __restrict__ tw) {
    int m = blockIdx.x, b = blockIdx.y, t = threadIdx.x;
    float T1 = g_T1[b];
    float pos = tw[b * Mw + m] / T1;
    float x = fminf(fmaxf(pos, 0.f), 1.f) * (float)(N1 - 1);
    int i0 = min(max((int)x, 0), N1 - 2);
    float w = x - (float)i0;
    const float* r0 = s1f + ((size_t)b * N1 + i0) * Dd;
    float f0 = r0[t], f1 = r0[Dd + t];
    g_s1at[b][m][t] = f0 * (1.f - w) + f1 * w;
}

// ---------------- kernel 2: node costs (smem-staged s1at, warp-per-k) ----------------
__global__ void k2_node(const float* __restrict__ s2f, const float* __restrict__ glb_lb,
                        const float* __restrict__ glb_ub, const float* __restrict__ tw) {
    int b = blockIdx.y;
    int tid = threadIdx.x;
    int wq = tid >> 5, lane = tid & 31;
    int k = blockIdx.x * 8 + wq;
    __shared__ float s_lb[Mw], s_w[Mw], s_tw[Mw];
    __shared__ float4 s_s1[32][32];  // 32 m rows x 128 floats
    float T2 = g_T2[b];
    for (int i = tid; i < Mw; i += 256) {
        float lb = glb_lb[b * Mw + i] * T2;
        float ub = glb_ub[b * Mw + i] * T2;
        s_lb[i] = lb; s_w[i] = ub - lb; s_tw[i] = tw[b * Mw + i];
    }
    float frk = (float)k / 95.0f;
    float invT2 = 1.f / T2;
    const float* s2b = s2f + (size_t)b * N2 * Dd;
    int i0p = -1;
    float4 f0v = make_float4(0.f, 0.f, 0.f, 0.f), f1v = f0v;
    for (int mc = 0; mc < Mw; mc += 32) {
        __syncthreads();
        const float4* src = (const float4*)&g_s1at[b][mc][0];
        for (int idx = tid; idx < 32 * 32; idx += 256)
            s_s1[idx >> 5][idx & 31] = src[idx];
        __syncthreads();
        for (int m0 = 0; m0 < 32; m0 += 4) {
            float acc[4], tks[4];
            #pragma unroll
            for (int u = 0; u < 4; u++) {
                int m = mc + m0 + u;
                float tk = s_lb[m] + s_w[m] * frk;
                tks[u] = tk;
                float x = fminf(fmaxf(tk * invT2, 0.f), 1.f) * (float)(N2 - 1);
                int i0 = min(max((int)x, 0), N2 - 2);
                float w = x - (float)i0;
                if (i0 != i0p) {
                    f0v = *((const float4*)(s2b + (size_t)i0 * Dd) + lane);
                    f1v = *((const float4*)(s2b + (size_t)(i0 + 1) * Dd) + lane);
                    i0p = i0;
                }
                float4 s1v = s_s1[m0 + u][lane];
                float d0 = s1v.x - (f0v.x + w * (f1v.x - f0v.x));
                float d1 = s1v.y - (f0v.y + w * (f1v.y - f0v.y));
                float d2 = s1v.z - (f0v.z + w * (f1v.z - f0v.z));
                float d3 = s1v.w - (f0v.w + w * (f1v.w - f0v.w));
                acc[u] = fmaf(d0, d0, fmaf(d1, d1, fmaf(d2, d2, d3 * d3)));
            }
            for (int o = 16; o; o >>= 1) {
                #pragma unroll
                for (int u = 0; u < 4; u++)
                    acc[u] += __shfl_xor_sync(FULLM, acc[u], o);
            }
            if (lane == 0) {
                #pragma unroll
                for (int u = 0; u < 4; u++) {
                    int m = mc + m0 + u;
                    float twm = s_tw[m];
                    float wt = 0.f;
                    if (m > 0) wt += twm - s_tw[m - 1];
                    if (m < Mw - 1) wt += s_tw[m + 1] - twm;
                    wt *= 0.5f;
                    float node = acc[u] * wt;
                    float tk = tks[u];
                    if (m == 0) node += BARRIERc * tk * tk;
                    if (m == Mw - 1) { float dd = tk - T2; node += BARRIERc * dd * dd; }
                    g_node[b][m][k] = node;
                }
            }
        }
    }
}

// ---------------- edge cost ----------------
__device__ __forceinline__ float edge_fn(float slope, float gub, float rwd) {
    float d1 = slope - 1.f;
    float n1 = fminf(slope, 0.f);
    float r2 = fmaxf(slope - gub, 0.f);
    float pen = fmaf(n1, n1, r2 * r2);
    return fmaf(BARRIERc, pen, rwd * d1 * d1);
}

// general windowed softmin (fallback)
__device__ __forceinline__ float softmin_win(
    const float* __restrict__ sa, const float* __restrict__ sfrac,
    int jlo, int jhi, float tref, float sgn, float invd,
    float lbp, float wp, float gub, float rwd) {
    float mval = INFf, ssum = 0.f;
    for (int j = jlo; j <= jhi; j++) {
        float tpj = lbp + wp * sfrac[j];
        float slope = sgn * (tref - tpj) * invd;
        float e = edge_fn(slope, gub, rwd);
        float xv = sa[j] + e;
        float dlt = xv - mval;
        float tt = ex2a(-fabsf(dlt) * IG2);
        if (dlt < 0.f) { ssum = fmaf(ssum, tt, 1.f); mval = xv; }
        else           { ssum += tt; }
    }
    return mval - GLN2 * lg2a(ssum);
}

// 4-candidate softmin with W branching. x[t] already masked (INF invalid).
__device__ __forceinline__ float softmin4(const float x[4], int d0t, int W) {
    if (W == 1) {
        return fminf(fminf(x[0], x[1]), fminf(x[2], x[3]));
    } else if (W == 2) {
        int t0 = d0t + 1;  // 0..2
        float xlo = (t0 == 0) ? x[0] : ((t0 == 1) ? x[1] : x[2]);
        float xhi = (t0 == 0) ? x[1] : ((t0 == 1) ? x[2] : x[3]);
        float mv = fminf(xlo, xhi);
        float ss = 1.f + ex2a(-fabsf(xlo - xhi) * IG2);
        return mv - GLN2 * lg2a(ss);
    } else {
        float mv = fminf(fminf(x[0], x[1]), fminf(x[2], x[3]));
        float ss = ex2a((mv - x[0]) * IG2) + ex2a((mv - x[1]) * IG2)
                 + ex2a((mv - x[2]) * IG2) + ex2a((mv - x[3]) * IG2);
        return mv - GLN2 * lg2a(ss);
    }
}

// ---------------- kernel 3: single-warp all-register scans ----------------
// layout: lane holds k = 3*lane + r, r in {0,1,2}
__global__ void k3_scan(const float* __restrict__ tw, const float* __restrict__ reg_wt,
                        const float* __restrict__ lgu, const float* __restrict__ glb_lb,
                        const float* __restrict__ glb_ub) {
    int dir = blockIdx.x, b = blockIdx.y;
    int lane = threadIdx.x;  // 32 threads
    __shared__ float s_lb[Mw], s_w[Mw], s_tw[Mw], s_frac[Kd], s_a[Kd];
    float T2 = g_T2[b];
    for (int i = lane; i < Mw; i += 32) {
        float lb = glb_lb[b * Mw + i] * T2;
        float ub = glb_ub[b * Mw + i] * T2;
        s_lb[i] = lb; s_w[i] = ub - lb; s_tw[i] = tw[b * Mw + i];
    }
    for (int i = lane; i < Kd; i += 32) s_frac[i] = (float)i / 95.0f;
    __syncwarp();
    float rw = reg_wt[b], gub = lgu[b];
    int kb = 3 * lane;
    float fr0 = (float)kb / 95.0f, fr1 = (float)(kb + 1) / 95.0f, fr2 = (float)(kb + 2) / 95.0f;
    bool gl = (lane >= 1), gr = (lane <= 30);

    if (dir == 0) {
        // -------- forward --------
        // j-range validity, fwd: src j = k - delta, t = delta+1
        // r0 srcs {a1,a0,p2,p1}; r1 {a2,a1,a0,p2}; r2 {n0,a2,a1,a0}
        bool v0[4] = {true, true, gl, gl};
        bool v1[4] = {true, true, true, gl};
        bool v2[4] = {gr, true, true, true};
        float a0 = g_node[b][0][kb], a1 = g_node[b][0][kb + 1], a2 = g_node[b][0][kb + 2];
        g_alpha[b][0][kb] = a0; g_alpha[b][0][kb + 1] = a1; g_alpha[b][0][kb + 2] = a2;
        float mina = o2f(__reduce_min_sync(FULLM, f2o(fminf(fminf(a0, a1), a2))));
        float maxa = o2f(__reduce_max_sync(FULLM, f2o(fmaxf(fmaxf(a0, a1), a2))));
        float nn0 = g_node[b][1][kb], nn1 = g_node[b][1][kb + 1], nn2r = g_node[b][1][kb + 2];
        float lbp = s_lb[0], wp = s_w[0], twp = s_tw[0];
        for (int i = 0; i < Mw - 1; i++) {
            float lbn = s_lb[i + 1], wn = s_w[i + 1], twn = s_tw[i + 1];
            float dtw = twn - twp;
            float invd = __fdividef(1.f, dtw);
            float rwd = rw * dtw;
            float pf0 = 0.f, pf1 = 0.f, pf2 = 0.f;
            if (i + 2 < Mw) {
                pf0 = g_node[b][i + 2][kb]; pf1 = g_node[b][i + 2][kb + 1]; pf2 = g_node[b][i + 2][kb + 2];
            }
            float marg = sqrta((maxa - mina + 15.f) * (1.f / BARRIERc));
            bool uni = (lbn == lbp) && (wn == wp) && (wp > 0.f);
            float u95 = 95.f * dtw * __fdividef(1.f, wp);
            int d0t = -__float2int_rd(marg * u95);
            int dmt = __float2int_rd((gub + marg) * u95);
            float an0, an1, an2;
            if (uni && d0t >= -1 && dmt <= 2 && dmt >= d0t) {
                int W = dmt - d0t + 1;
                float sinv = wp * invd * (1.0f / 95.0f);
                float e[4];
                bool iw[4];
                #pragma unroll
                for (int t = 0; t < 4; t++) {
                    int dlt = t - 1;
                    e[t] = edge_fn((float)dlt * sinv, gub, rwd);
                    iw[t] = (dlt >= d0t) && (dlt <= dmt);
                }
                float p1 = __shfl_up_sync(FULLM, a1, 1);
                float p2 = __shfl_up_sync(FULLM, a2, 1);
                float n0 = __shfl_down_sync(FULLM, a0, 1);
                float x0[4], x1[4], x2[4];
                x0[0] = (iw[0] && v0[0]) ? a1 + e[0] : INFf;
                x0[1] = (iw[1] && v0[1]) ? a0 + e[1] : INFf;
                x0[2] = (iw[2] && v0[2]) ? p2 + e[2] : INFf;
                x0[3] = (iw[3] && v0[3]) ? p1 + e[3] : INFf;
                x1[0] = (iw[0] && v1[0]) ? a2 + e[0] : INFf;
                x1[1] = (iw[1] && v1[1]) ? a1 + e[1] : INFf;
                x1[2] = (iw[2] && v1[2]) ? a0 + e[2] : INFf;
                x1[3] = (iw[3] && v1[3]) ? p2 + e[3] : INFf;
                x2[0] = (iw[0] && v2[0]) ? n0 + e[0] : INFf;
                x2[1] = (iw[1] && v2[1]) ? a2 + e[1] : INFf;
                x2[2] = (iw[2] && v2[2]) ? a1 + e[2] : INFf;
                x2[3] = (iw[3] && v2[3]) ? a0 + e[3] : INFf;
                an0 = nn0 + softmin4(x0, d0t, W);
                an1 = nn1 + softmin4(x1, d0t, W);
                an2 = nn2r + softmin4(x2, d0t, W);
            } else {
                s_a[kb] = a0; s_a[kb + 1] = a1; s_a[kb + 2] = a2;
                __syncwarp();
                float inv95wp = __fdividef(95.0f, wp);
                bool degen = !(wp > 0.f);
                float loOff = (gub + marg) * dtw;
                float hiOff = marg * dtw;
                float res[3];
                float frs[3] = {fr0, fr1, fr2};
                #pragma unroll
                for (int r = 0; r < 3; r++) {
                    float tnk = lbn + wn * frs[r];
                    int jlo = max(0, __float2int_ru((tnk - loOff - lbp) * inv95wp));
                    int jhi = min(Kd - 1, __float2int_rd((tnk + hiOff - lbp) * inv95wp));
                    if (degen) { jlo = 0; jhi = Kd - 1; }
                    if (jhi < jlo) { int c = min(Kd - 1, max(0, jlo)); jlo = max(0, c - 1); jhi = min(Kd - 1, c + 1); }
                    res[r] = softmin_win(s_a, s_frac, jlo, jhi, tnk, 1.f, invd, lbp, wp, gub, rwd);
                }
                an0 = nn0 + res[0]; an1 = nn1 + res[1]; an2 = nn2r + res[2];
                __syncwarp();
            }
            g_alpha[b][i + 1][kb] = an0; g_alpha[b][i + 1][kb + 1] = an1; g_alpha[b][i + 1][kb + 2] = an2;
            mina = o2f(__reduce_min_sync(FULLM, f2o(fminf(fminf(an0, an1), an2))));
            maxa = o2f(__reduce_max_sync(FULLM, f2o(fmaxf(fmaxf(an0, an1), an2))));
            a0 = an0; a1 = an1; a2 = an2;
            nn0 = pf0; nn1 = pf1; nn2r = pf2;
            lbp = lbn; wp = wn; twp = twn;
        }
    } else {
        // -------- backward --------
        // src kq = k + delta: r0 {p2,a0,a1,a2}; r1 {a0,a1,a2,n0}; r2 {a1,a2,n0,n1}
        bool v0[4] = {gl, true, true, true};
        bool v1[4] = {true, true, true, gr};
        bool v2[4] = {true, true, gr, gr};
        float a0 = g_node[b][Mw - 1][kb], a1 = g_node[b][Mw - 1][kb + 1], a2 = g_node[b][Mw - 1][kb + 2];
        g_beta[b][Mw - 1][kb] = 0.f; g_beta[b][Mw - 1][kb + 1] = 0.f; g_beta[b][Mw - 1][kb + 2] = 0.f;
        float mina = o2f(__reduce_min_sync(FULLM, f2o(fminf(fminf(a0, a1), a2))));
        float maxa = o2f(__reduce_max_sync(FULLM, f2o(fmaxf(fmaxf(a0, a1), a2))));
        float ni0 = g_node[b][Mw - 2][kb], ni1 = g_node[b][Mw - 2][kb + 1], ni2 = g_node[b][Mw - 2][kb + 2];
        float lbp = s_lb[Mw - 1], wp = s_w[Mw - 1], twp = s_tw[Mw - 1];
        for (int i = Mw - 2; i >= 0; i--) {
            float lbj = s_lb[i], wj = s_w[i], twj = s_tw[i];
            float dtw = twp - twj;
            float invd = __fdividef(1.f, dtw);
            float rwd = rw * dtw;
            float pf0 = 0.f, pf1 = 0.f, pf2 = 0.f;
            if (i > 0) {
                pf0 = g_node[b][i - 1][kb]; pf1 = g_node[b][i - 1][kb + 1]; pf2 = g_node[b][i - 1][kb + 2];
            }
            float marg = sqrta((maxa - mina + 15.f) * (1.f / BARRIERc));
            bool uni = (lbj == lbp) && (wj == wp) && (wp > 0.f);
            float u95 = 95.f * dtw * __fdividef(1.f, wp);
            int d0t = -__float2int_rd(marg * u95);
            int dmt = __float2int_rd((gub + marg) * u95);
            float bn0, bn1, bn2;
            if (uni && d0t >= -1 && dmt <= 2 && dmt >= d0t) {
                int W = dmt - d0t + 1;
                float sinv = wp * invd * (1.0f / 95.0f);
                float e[4];
                bool iw[4];
                #pragma unroll
                for (int t = 0; t < 4; t++) {
                    int dlt = t - 1;
                    e[t] = edge_fn((float)dlt * sinv, gub, rwd);
                    iw[t] = (dlt >= d0t) && (dlt <= dmt);
                }
                float p2 = __shfl_up_sync(FULLM, a2, 1);
                float n0 = __shfl_down_sync(FULLM, a0, 1);
                float n1 = __shfl_down_sync(FULLM, a1, 1);
                float x0[4], x1[4], x2[4];
                x0[0] = (iw[0] && v0[0]) ? p2 + e[0] : INFf;
                x0[1] = (iw[1] && v0[1]) ? a0 + e[1] : INFf;
                x0[2] = (iw[2] && v0[2]) ? a1 + e[2] : INFf;
                x0[3] = (iw[3] && v0[3]) ? a2 + e[3] : INFf;
                x1[0] = (iw[0] && v1[0]) ? a0 + e[0] : INFf;
                x1[1] = (iw[1] && v1[1]) ? a1 + e[1] : INFf;
                x1[2] = (iw[2] && v1[2]) ? a2 + e[2] : INFf;
                x1[3] = (iw[3] && v1[3]) ? n0 + e[3] : INFf;
                x2[0] = (iw[0] && v2[0]) ? a1 + e[0] : INFf;
                x2[1] = (iw[1] && v2[1]) ? a2 + e[1] : INFf;
                x2[2] = (iw[2] && v2[2]) ? n0 + e[2] : INFf;
                x2[3] = (iw[3] && v2[3]) ? n1 + e[3] : INFf;
                bn0 = softmin4(x0, d0t, W);
                bn1 = softmin4(x1, d0t, W);
                bn2 = softmin4(x2, d0t, W);
            } else {
                s_a[kb] = a0; s_a[kb + 1] = a1; s_a[kb + 2] = a2;
                __syncwarp();
                float inv95wp = __fdividef(95.0f, wp);
                bool degen = !(wp > 0.f);
                float loOff = marg * dtw;
                float hiOff = (gub + marg) * dtw;
                float res[3];
                float frs[3] = {fr0, fr1, fr2};
                #pragma unroll
                for (int r = 0; r < 3; r++) {
                    float tj = lbj + wj * frs[r];
                    int klo = max(0, __float2int_ru((tj - loOff - lbp) * inv95wp));
                    int khi = min(Kd - 1, __float2int_rd((tj + hiOff - lbp) * inv95wp));
                    if (degen) { klo = 0; khi = Kd - 1; }
                    if (khi < klo) { int cc = min(Kd - 1, max(0, klo)); klo = max(0, cc - 1); khi = min(Kd - 1, cc + 1); }
                    res[r] = softmin_win(s_a, s_frac, klo, khi, tj, -1.f, invd, lbp, wp, gub, rwd);
                }
                bn0 = res[0]; bn1 = res[1]; bn2 = res[2];
                __syncwarp();
            }
            g_beta[b][i][kb] = bn0; g_beta[b][i][kb + 1] = bn1; g_beta[b][i][kb + 2] = bn2;
            float c0 = ni0 + bn0, c1 = ni1 + bn1, c2 = ni2 + bn2;
            mina = o2f(__reduce_min_sync(FULLM, f2o(fminf(fminf(c0, c1), c2))));
            maxa = o2f(__reduce_max_sync(FULLM, f2o(fmaxf(fmaxf(c0, c1), c2))));
            a0 = c0; a1 = c1; a2 = c2;
            ni0 = pf0; ni1 = pf1; ni2 = pf2;
            lbp = lbj; wp = wj; twp = twj;
        }
    }
}

// ---------------- kernel 4 ----------------
__global__ void k4_out(const float* __restrict__ glb_lb, const float* __restrict__ glb_ub,
                       float* __restrict__ out) {
    int m = blockIdx.x, b = blockIdx.y, lane = threadIdx.x;
    float T2 = g_T2[b];
    float lb = glb_lb[b * Mw + m] * T2;
    float ub = glb_ub[b * Mw + m] * T2;
    float w = ub - lb;
    float v[3], ta[3];
    #pragma unroll
    for (int r = 0; r < 3; r++) {
        int k = lane + 32 * r;
        v[r] = g_alpha[b][m][k] + g_beta[b][m][k];
        ta[r] = lb + w * ((float)k / 95.0f);
    }
    float l = fminf(fminf(v[0], v[1]), v[2]);
    float vmin = o2f(__reduce_min_sync(FULLM, f2o(l)));
    float ps = 0.f, pts = 0.f;
    #pragma unroll
    for (int r = 0; r < 3; r++) {
        float p = ex2a((vmin - v[r]) * IG2);
        ps += p;
        pts = fmaf(p, ta[r], pts);
    }
    for (int o = 16; o; o >>= 1) {
        ps += __shfl_xor_sync(FULLM, ps, o);
        pts += __shfl_xor_sync(FULLM, pts, o);
    }
    if (lane == 0) out[b * Mw + m] = pts / ps;
}

extern "C" void kernel_launch(void* const* d_in, const int* in_sizes, int n_in,
                              void* d_out, int out_size) {
    const float* s1f    = (const float*)d_in[0];
    const float* s2f    = (const float*)d_in[1];
    const float* regw   = (const float*)d_in[2];
    const float* glb_lb = (const float*)d_in[3];
    const float* glb_ub = (const float*)d_in[4];
    const float* lgu    = (const float*)d_in[5];
    const float* t1     = (const float*)d_in[6];
    const float* t2     = (const float*)d_in[7];
    const float* twf    = (const float*)d_in[8];
    float* out = (float*)d_out;

    k0_maxes<<<Bn, 256>>>(t1, t2);
    k1_prep<<<dim3(Mw, Bn), Dd>>>(s1f, twf);
    k2_node<<<dim3(Kd / 8, Bn), 256>>>(s2f, glb_lb, glb_ub, twf);
    k3_scan<<<dim3(2, Bn), 32>>>(twf, regw, lgu, glb_lb, glb_ub);
    k4_out<<<dim3(Mw, Bn), 32>>>(glb_lb, glb_ub, out);
}

// round 6
// speedup vs baseline: 3.4088x; 1.0127x over previous
#include <cuda_runtime.h>
#include <math.h>

#define Bn 32
#define N1 512
#define N2 512
#define Dd 128
#define Mw 256
#define Kd 96
#define BARRIERc 10000.0f

#define IG2 14.4269504088896f   /* log2(e)/gamma */
#define GLN2 0.069314718055995f /* gamma*ln(2)   */
#define INFf __int_as_float(0x7f800000)
#define FULLM 0xffffffffu

__device__ float g_T1[Bn], g_T2[Bn];
__device__ float g_node[Bn][Mw][Kd];
__device__ float g_alpha[Bn][Mw][Kd];
__device__ float g_beta[Bn][Mw][Kd];

__device__ __forceinline__ float ex2a(float x) { float y; asm("ex2.approx.f32 %0, %1;" : "=f"(y) : "f"(x)); return y; }
__device__ __forceinline__ float lg2a(float x) { float y; asm("lg2.approx.f32 %0, %1;" : "=f"(y) : "f"(x)); return y; }
__device__ __forceinline__ float sqrta(float x) { float y; asm("sqrt.approx.f32 %0, %1;" : "=f"(y) : "f"(x)); return y; }

__device__ __forceinline__ unsigned f2o(float x) {
    unsigned u = __float_as_uint(x);
    return (u & 0x80000000u) ? ~u : (u | 0x80000000u);
}
__device__ __forceinline__ float o2f(unsigned v) {
    return __uint_as_float((v & 0x80000000u) ? (v ^ 0x80000000u) : ~v);
}

// ---------------- kernel 0 ----------------
__global__ void k0_maxes(const float* __restrict__ t1, const float* __restrict__ t2) {
    int b = blockIdx.x, t = threadIdx.x;
    float m1 = -3.4e38f, m2 = -3.4e38f;
    for (int i = t; i < N1; i += 256) m1 = fmaxf(m1, t1[b * N1 + i]);
    for (int i = t; i < N2; i += 256) m2 = fmaxf(m2, t2[b * N2 + i]);
    __shared__ float s1[8], s2[8];
    for (int o = 16; o; o >>= 1) {
        m1 = fmaxf(m1, __shfl_xor_sync(FULLM, m1, o));
        m2 = fmaxf(m2, __shfl_xor_sync(FULLM, m2, o));
    }
    if ((t & 31) == 0) { s1[t >> 5] = m1; s2[t >> 5] = m2; }
    __syncthreads();
    if (t == 0) {
        float a = s1[0], c = s2[0];
        for (int w = 1; w < 8; w++) { a = fmaxf(a, s1[w]); c = fmaxf(c, s2[w]); }
        g_T1[b] = a; g_T2[b] = c;
    }
}

// ---------------- kernel 2: node costs (fused s1 interp + smem staging) ----------------
__global__ void k2_node(const float* __restrict__ s1f, const float* __restrict__ s2f,
                        const float* __restrict__ glb_lb, const float* __restrict__ glb_ub,
                        const float* __restrict__ tw) {
    int b = blockIdx.y;
    int tid = threadIdx.x;
    int wq = tid >> 5, lane = tid & 31;
    int k = blockIdx.x * 8 + wq;
    __shared__ float s_lb[Mw], s_w[Mw], s_tw[Mw];
    __shared__ int   s_i0[32];
    __shared__ float s_w1[32];
    __shared__ float4 s_s1[32][32];
    float T2 = g_T2[b], T1 = g_T1[b];
    for (int i = tid; i < Mw; i += 256) {
        float lb = glb_lb[b * Mw + i] * T2;
        float ub = glb_ub[b * Mw + i] * T2;
        s_lb[i] = lb; s_w[i] = ub - lb; s_tw[i] = tw[b * Mw + i];
    }
    __syncthreads();
    float frk = (float)k / 95.0f;
    float invT2 = 1.f / T2, invT1 = 1.f / T1;
    const float* s2b = s2f + (size_t)b * N2 * Dd;
    const float* s1b = s1f + (size_t)b * N1 * Dd;
    int i0p = -1;
    float4 f0v = make_float4(0.f, 0.f, 0.f, 0.f), f1v = f0v;
    for (int mc = 0; mc < Mw; mc += 32) {
        __syncthreads();
        if (tid < 32) {
            float pos = s_tw[mc + tid] * invT1;
            float x = fminf(fmaxf(pos, 0.f), 1.f) * (float)(N1 - 1);
            int i0 = min(max((int)x, 0), N1 - 2);
            s_i0[tid] = i0;
            s_w1[tid] = x - (float)i0;
        }
        __syncthreads();
        for (int idx = tid; idx < 1024; idx += 256) {
            int ml = idx >> 5, l4 = idx & 31;
            const float4* r0 = (const float4*)(s1b + (size_t)s_i0[ml] * Dd);
            float4 f0 = r0[l4], f1 = r0[32 + l4];
            float ww = s_w1[ml];
            float4 o;
            o.x = f0.x + ww * (f1.x - f0.x);
            o.y = f0.y + ww * (f1.y - f0.y);
            o.z = f0.z + ww * (f1.z - f0.z);
            o.w = f0.w + ww * (f1.w - f0.w);
            s_s1[ml][l4] = o;
        }
        __syncthreads();
        for (int m0 = 0; m0 < 32; m0 += 4) {
            float acc[4], tks[4];
            #pragma unroll
            for (int u = 0; u < 4; u++) {
                int m = mc + m0 + u;
                float tk = s_lb[m] + s_w[m] * frk;
                tks[u] = tk;
                float x = fminf(fmaxf(tk * invT2, 0.f), 1.f) * (float)(N2 - 1);
                int i0 = min(max((int)x, 0), N2 - 2);
                float w = x - (float)i0;
                if (i0 != i0p) {
                    f0v = *((const float4*)(s2b + (size_t)i0 * Dd) + lane);
                    f1v = *((const float4*)(s2b + (size_t)(i0 + 1) * Dd) + lane);
                    i0p = i0;
                }
                float4 s1v = s_s1[m0 + u][lane];
                float d0 = s1v.x - (f0v.x + w * (f1v.x - f0v.x));
                float d1 = s1v.y - (f0v.y + w * (f1v.y - f0v.y));
                float d2 = s1v.z - (f0v.z + w * (f1v.z - f0v.z));
                float d3 = s1v.w - (f0v.w + w * (f1v.w - f0v.w));
                acc[u] = fmaf(d0, d0, fmaf(d1, d1, fmaf(d2, d2, d3 * d3)));
            }
            for (int o = 16; o; o >>= 1) {
                #pragma unroll
                for (int u = 0; u < 4; u++)
                    acc[u] += __shfl_xor_sync(FULLM, acc[u], o);
            }
            if (lane == 0) {
                #pragma unroll
                for (int u = 0; u < 4; u++) {
                    int m = mc + m0 + u;
                    float twm = s_tw[m];
                    float wt = 0.f;
                    if (m > 0) wt += twm - s_tw[m - 1];
                    if (m < Mw - 1) wt += s_tw[m + 1] - twm;
                    wt *= 0.5f;
                    float node = acc[u] * wt;
                    float tk = tks[u];
                    if (m == 0) node += BARRIERc * tk * tk;
                    if (m == Mw - 1) { float dd = tk - T2; node += BARRIERc * dd * dd; }
                    g_node[b][m][k] = node;
                }
            }
        }
    }
}

// ---------------- edge cost ----------------
__device__ __forceinline__ float edge_fn(float slope, float gub, float rwd) {
    float d1 = slope - 1.f;
    float n1 = fminf(slope, 0.f);
    float r2 = fmaxf(slope - gub, 0.f);
    float pen = fmaf(n1, n1, r2 * r2);
    return fmaf(BARRIERc, pen, rwd * d1 * d1);
}

// general windowed softmin (cold fallback)
__device__ __forceinline__ float softmin_win(
    const float* __restrict__ sa, const float* __restrict__ sfrac,
    int jlo, int jhi, float tref, float sgn, float invd,
    float lbp, float wp, float gub, float rwd) {
    float mval = INFf, ssum = 0.f;
    for (int j = jlo; j <= jhi; j++) {
        float tpj = lbp + wp * sfrac[j];
        float slope = sgn * (tref - tpj) * invd;
        float e = edge_fn(slope, gub, rwd);
        float xv = sa[j] + e;
        float dlt = xv - mval;
        float tt = ex2a(-fabsf(dlt) * IG2);
        if (dlt < 0.f) { ssum = fmaf(ssum, tt, 1.f); mval = xv; }
        else           { ssum += tt; }
    }
    return mval - GLN2 * lg2a(ssum);
}

__device__ __forceinline__ float sm4(float x0, float x1, float x2, float x3) {
    float mv = fminf(fminf(x0, x1), fminf(x2, x3));
    float ss = ex2a((mv - x0) * IG2) + ex2a((mv - x1) * IG2)
             + ex2a((mv - x2) * IG2) + ex2a((mv - x3) * IG2);
    return mv - GLN2 * lg2a(ss);
}

// ---------------- kernel 3: single-warp scans, unconditional fixed window ----------------
// layout: lane holds k = 3*lane + r
__global__ void k3_scan(const float* __restrict__ tw, const float* __restrict__ reg_wt,
                        const float* __restrict__ lgu, const float* __restrict__ glb_lb,
                        const float* __restrict__ glb_ub) {
    int dir = blockIdx.x, b = blockIdx.y;
    int lane = threadIdx.x;
    __shared__ float s_lb[Mw], s_w[Mw], s_tw[Mw], s_frac[Kd], s_a[Kd];
    float T2 = g_T2[b];
    for (int i = lane; i < Mw; i += 32) {
        float lb = glb_lb[b * Mw + i] * T2;
        float ub = glb_ub[b * Mw + i] * T2;
        s_lb[i] = lb; s_w[i] = ub - lb; s_tw[i] = tw[b * Mw + i];
    }
    for (int i = lane; i < Kd; i += 32) s_frac[i] = (float)i / 95.0f;
    __syncwarp();
    float rw = reg_wt[b], gub = lgu[b];
    float gmin1 = fmaxf(1.f, gub);
    int kb = 3 * lane;
    float fr0 = (float)kb / 95.0f, fr1 = (float)(kb + 1) / 95.0f, fr2 = (float)(kb + 2) / 95.0f;
    bool gl = (lane >= 1), gr = (lane <= 30);

    if (dir == 0) {
        // -------- forward --------
        float a0 = g_node[b][0][kb], a1 = g_node[b][0][kb + 1], a2 = g_node[b][0][kb + 2];
        g_alpha[b][0][kb] = a0; g_alpha[b][0][kb + 1] = a1; g_alpha[b][0][kb + 2] = a2;
        float mina = o2f(__reduce_min_sync(FULLM, f2o(fminf(fminf(a0, a1), a2))));
        float maxa = o2f(__reduce_max_sync(FULLM, f2o(fmaxf(fmaxf(a0, a1), a2))));
        float nn0 = g_node[b][1][kb], nn1 = g_node[b][1][kb + 1], nn2 = g_node[b][1][kb + 2];
        int i2 = min(2, Mw - 1);
        float nf0 = g_node[b][i2][kb], nf1 = g_node[b][i2][kb + 1], nf2 = g_node[b][i2][kb + 2];
        float lbp = s_lb[0], wp = s_w[0], twp = s_tw[0];
        for (int i = 0; i < Mw - 1; i++) {
            float lbn = s_lb[i + 1], wn = s_w[i + 1], twn = s_tw[i + 1];
            float dtw = twn - twp;
            float invd = __fdividef(1.f, dtw);
            float rwd = rw * dtw;
            int ip = min(i + 3, Mw - 1);
            float nl0 = g_node[b][ip][kb], nl1 = g_node[b][ip][kb + 1], nl2 = g_node[b][ip][kb + 2];
            bool uni = (lbn == lbp) && (wn == wp) && (wp > 0.f);
            float sinv = wp * invd * (1.0f / 95.0f);
            float e0 = edge_fn(-sinv, gub, rwd);          // delta = -1
            float e1 = rwd;                                // delta = 0 (slope 0)
            float e2 = edge_fn(sinv, gub, rwd);            // delta = 1
            float e3 = edge_fn(2.f * sinv, gub, rwd);      // delta = 2
            // safety check (off critical path)
            float thr = maxa - mina + 15.f;
            float sl3 = 3.f * sinv;
            bool ok = uni && (edge_fn(-2.f * sinv, gub, rwd) >= thr)
                          && (edge_fn(sl3, gub, rwd) >= thr) && (sl3 >= gmin1);
            // neighbor values
            float p1 = __shfl_up_sync(FULLM, a1, 1);
            float p2 = __shfl_up_sync(FULLM, a2, 1);
            float n0 = __shfl_down_sync(FULLM, a0, 1);
            // fwd: k gets j = k - delta, t = delta+1 maps e[t]
            float an0 = nn0 + sm4(a1 + e0, a0 + e1, gl ? p2 + e2 : INFf, gl ? p1 + e3 : INFf);
            float an1 = nn1 + sm4(a2 + e0, a1 + e1, a0 + e2, gl ? p2 + e3 : INFf);
            float an2 = nn2 + sm4(gr ? n0 + e0 : INFf, a2 + e1, a1 + e2, a0 + e3);
            if (!__all_sync(FULLM, ok)) {
                s_a[kb] = a0; s_a[kb + 1] = a1; s_a[kb + 2] = a2;
                __syncwarp();
                float marg = sqrta(thr * (1.f / BARRIERc));
                float inv95wp = __fdividef(95.0f, wp);
                bool degen = !(wp > 0.f);
                float loOff = (gub + marg) * dtw;
                float hiOff = marg * dtw;
                float res[3];
                float frs[3] = {fr0, fr1, fr2};
                #pragma unroll
                for (int r = 0; r < 3; r++) {
                    float tnk = lbn + wn * frs[r];
                    int jlo = max(0, __float2int_ru((tnk - loOff - lbp) * inv95wp));
                    int jhi = min(Kd - 1, __float2int_rd((tnk + hiOff - lbp) * inv95wp));
                    if (degen) { jlo = 0; jhi = Kd - 1; }
                    if (jhi < jlo) { int c = min(Kd - 1, max(0, jlo)); jlo = max(0, c - 1); jhi = min(Kd - 1, c + 1); }
                    res[r] = softmin_win(s_a, s_frac, jlo, jhi, tnk, 1.f, invd, lbp, wp, gub, rwd);
                }
                an0 = nn0 + res[0]; an1 = nn1 + res[1]; an2 = nn2 + res[2];
                __syncwarp();
            }
            g_alpha[b][i + 1][kb] = an0; g_alpha[b][i + 1][kb + 1] = an1; g_alpha[b][i + 1][kb + 2] = an2;
            mina = o2f(__reduce_min_sync(FULLM, f2o(fminf(fminf(an0, an1), an2))));
            maxa = o2f(__reduce_max_sync(FULLM, f2o(fmaxf(fmaxf(an0, an1), an2))));
            a0 = an0; a1 = an1; a2 = an2;
            nn0 = nf0; nn1 = nf1; nn2 = nf2;
            nf0 = nl0; nf1 = nl1; nf2 = nl2;
            lbp = lbn; wp = wn; twp = twn;
        }
    } else {
        // -------- backward --------
        float a0 = g_node[b][Mw - 1][kb], a1 = g_node[b][Mw - 1][kb + 1], a2 = g_node[b][Mw - 1][kb + 2];
        g_beta[b][Mw - 1][kb] = 0.f; g_beta[b][Mw - 1][kb + 1] = 0.f; g_beta[b][Mw - 1][kb + 2] = 0.f;
        float mina = o2f(__reduce_min_sync(FULLM, f2o(fminf(fminf(a0, a1), a2))));
        float maxa = o2f(__reduce_max_sync(FULLM, f2o(fmaxf(fmaxf(a0, a1), a2))));
        float ni0 = g_node[b][Mw - 2][kb], ni1 = g_node[b][Mw - 2][kb + 1], ni2 = g_node[b][Mw - 2][kb + 2];
        int i3 = max(Mw - 3, 0);
        float nf0 = g_node[b][i3][kb], nf1 = g_node[b][i3][kb + 1], nf2 = g_node[b][i3][kb + 2];
        float lbp = s_lb[Mw - 1], wp = s_w[Mw - 1], twp = s_tw[Mw - 1];
        for (int i = Mw - 2; i >= 0; i--) {
            float lbj = s_lb[i], wj = s_w[i], twj = s_tw[i];
            float dtw = twp - twj;
            float invd = __fdividef(1.f, dtw);
            float rwd = rw * dtw;
            int ip = max(i - 2, 0);
            float nl0 = g_node[b][ip][kb], nl1 = g_node[b][ip][kb + 1], nl2 = g_node[b][ip][kb + 2];
            bool uni = (lbj == lbp) && (wj == wp) && (wp > 0.f);
            float sinv = wp * invd * (1.0f / 95.0f);
            float e0 = edge_fn(-sinv, gub, rwd);
            float e1 = rwd;
            float e2 = edge_fn(sinv, gub, rwd);
            float e3 = edge_fn(2.f * sinv, gub, rwd);
            float thr = maxa - mina + 15.f;
            float sl3 = 3.f * sinv;
            bool ok = uni && (edge_fn(-2.f * sinv, gub, rwd) >= thr)
                          && (edge_fn(sl3, gub, rwd) >= thr) && (sl3 >= gmin1);
            float p2 = __shfl_up_sync(FULLM, a2, 1);
            float n0 = __shfl_down_sync(FULLM, a0, 1);
            float n1 = __shfl_down_sync(FULLM, a1, 1);
            // bwd: k gets kq = k + delta
            float bn0 = sm4(gl ? p2 + e0 : INFf, a0 + e1, a1 + e2, a2 + e3);
            float bn1 = sm4(a0 + e0, a1 + e1, a2 + e2, gr ? n0 + e3 : INFf);
            float bn2 = sm4(a1 + e0, a2 + e1, gr ? n0 + e2 : INFf, gr ? n1 + e3 : INFf);
            if (!__all_sync(FULLM, ok)) {
                s_a[kb] = a0; s_a[kb + 1] = a1; s_a[kb + 2] = a2;
                __syncwarp();
                float marg = sqrta(thr * (1.f / BARRIERc));
                float inv95wp = __fdividef(95.0f, wp);
                bool degen = !(wp > 0.f);
                float loOff = marg * dtw;
                float hiOff = (gub + marg) * dtw;
                float res[3];
                float frs[3] = {fr0, fr1, fr2};
                #pragma unroll
                for (int r = 0; r < 3; r++) {
                    float tj = lbj + wj * frs[r];
                    int klo = max(0, __float2int_ru((tj - loOff - lbp) * inv95wp));
                    int khi = min(Kd - 1, __float2int_rd((tj + hiOff - lbp) * inv95wp));
                    if (degen) { klo = 0; khi = Kd - 1; }
                    if (khi < klo) { int cc = min(Kd - 1, max(0, klo)); klo = max(0, cc - 1); khi = min(Kd - 1, cc + 1); }
                    res[r] = softmin_win(s_a, s_frac, klo, khi, tj, -1.f, invd, lbp, wp, gub, rwd);
                }
                bn0 = res[0]; bn1 = res[1]; bn2 = res[2];
                __syncwarp();
            }
            g_beta[b][i][kb] = bn0; g_beta[b][i][kb + 1] = bn1; g_beta[b][i][kb + 2] = bn2;
            float c0 = ni0 + bn0, c1 = ni1 + bn1, c2 = ni2 + bn2;
            mina = o2f(__reduce_min_sync(FULLM, f2o(fminf(fminf(c0, c1), c2))));
            maxa = o2f(__reduce_max_sync(FULLM, f2o(fmaxf(fmaxf(c0, c1), c2))));
            a0 = c0; a1 = c1; a2 = c2;
            ni0 = nf0; ni1 = nf1; ni2 = nf2;
            nf0 = nl0; nf1 = nl1; nf2 = nl2;
            lbp = lbj; wp = wj; twp = twj;
        }
    }
}

// ---------------- kernel 4: 8 warps/block ----------------
__global__ void k4_out(const float* __restrict__ glb_lb, const float* __restrict__ glb_ub,
                       float* __restrict__ out) {
    int b = blockIdx.y;
    int wid = threadIdx.x >> 5, lane = threadIdx.x & 31;
    int m = blockIdx.x * 8 + wid;
    float T2 = g_T2[b];
    float lb = glb_lb[b * Mw + m] * T2;
    float ub = glb_ub[b * Mw + m] * T2;
    float w = ub - lb;
    float v[3], ta[3];
    #pragma unroll
    for (int r = 0; r < 3; r++) {
        int k = lane + 32 * r;
        v[r] = g_alpha[b][m][k] + g_beta[b][m][k];
        ta[r] = lb + w * ((float)k / 95.0f);
    }
    float l = fminf(fminf(v[0], v[1]), v[2]);
    float vmin = o2f(__reduce_min_sync(FULLM, f2o(l)));
    float ps = 0.f, pts = 0.f;
    #pragma unroll
    for (int r = 0; r < 3; r++) {
        float p = ex2a((vmin - v[r]) * IG2);
        ps += p;
        pts = fmaf(p, ta[r], pts);
    }
    for (int o = 16; o; o >>= 1) {
        ps += __shfl_xor_sync(FULLM, ps, o);
        pts += __shfl_xor_sync(FULLM, pts, o);
    }
    if (lane == 0) out[b * Mw + m] = pts / ps;
}

extern "C" void kernel_launch(void* const* d_in, const int* in_sizes, int n_in,
                              void* d_out, int out_size) {
    const float* s1f    = (const float*)d_in[0];
    const float* s2f    = (const float*)d_in[1];
    const float* regw   = (const float*)d_in[2];
    const float* glb_lb = (const float*)d_in[3];
    const float* glb_ub = (const float*)d_in[4];
    const float* lgu    = (const float*)d_in[5];
    const float* t1     = (const float*)d_in[6];
    const float* t2     = (const float*)d_in[7];
    const float* twf    = (const float*)d_in[8];
    float* out = (float*)d_out;

    k0_maxes<<<Bn, 256>>>(t1, t2);
    k2_node<<<dim3(Kd / 8, Bn), 256>>>(s1f, s2f, glb_lb, glb_ub, twf);
    k3_scan<<<dim3(2, Bn), 32>>>(twf, regw, lgu, glb_lb, glb_ub);
    k4_out<<<dim3(Mw / 8, Bn), 256>>>(glb_lb, glb_ub, out);
}

// round 7
// speedup vs baseline: 3.6423x; 1.0685x over previous
#include <cuda_runtime.h>
#include <math.h>

#define Bn 32
#define N1 512
#define N2 512
#define Dd 128
#define Mw 256
#define Kd 96
#define BARRIERc 10000.0f

#define IG2 14.4269504088896f   /* log2(e)/gamma */
#define GLN2 0.069314718055995f /* gamma*ln(2)   */
#define INFf __int_as_float(0x7f800000)
#define FULLM 0xffffffffu

__device__ float g_T1[Bn], g_T2[Bn];
__device__ float g_node[Bn][Mw][Kd];
__device__ float g_alpha[Bn][Mw][Kd];
__device__ float g_beta[Bn][Mw][Kd];

__device__ __forceinline__ float ex2a(float x) { float y; asm("ex2.approx.f32 %0, %1;" : "=f"(y) : "f"(x)); return y; }
__device__ __forceinline__ float lg2a(float x) { float y; asm("lg2.approx.f32 %0, %1;" : "=f"(y) : "f"(x)); return y; }
__device__ __forceinline__ float sqrta(float x) { float y; asm("sqrt.approx.f32 %0, %1;" : "=f"(y) : "f"(x)); return y; }

__device__ __forceinline__ unsigned f2o(float x) {
    unsigned u = __float_as_uint(x);
    return (u & 0x80000000u) ? ~u : (u | 0x80000000u);
}
__device__ __forceinline__ float o2f(unsigned v) {
    return __uint_as_float((v & 0x80000000u) ? (v ^ 0x80000000u) : ~v);
}

// ---------------- kernel 0 ----------------
__global__ void k0_maxes(const float* __restrict__ t1, const float* __restrict__ t2) {
    int b = blockIdx.x, t = threadIdx.x;
    float m1 = -3.4e38f, m2 = -3.4e38f;
    for (int i = t; i < N1; i += 256) m1 = fmaxf(m1, t1[b * N1 + i]);
    for (int i = t; i < N2; i += 256) m2 = fmaxf(m2, t2[b * N2 + i]);
    __shared__ float s1[8], s2[8];
    for (int o = 16; o; o >>= 1) {
        m1 = fmaxf(m1, __shfl_xor_sync(FULLM, m1, o));
        m2 = fmaxf(m2, __shfl_xor_sync(FULLM, m2, o));
    }
    if ((t & 31) == 0) { s1[t >> 5] = m1; s2[t >> 5] = m2; }
    __syncthreads();
    if (t == 0) {
        float a = s1[0], c = s2[0];
        for (int w = 1; w < 8; w++) { a = fmaxf(a, s1[w]); c = fmaxf(c, s2[w]); }
        g_T1[b] = a; g_T2[b] = c;
    }
}

// ---------------- kernel 2: node costs (fused s1 interp + smem staging) ----------------
__global__ void k2_node(const float* __restrict__ s1f, const float* __restrict__ s2f,
                        const float* __restrict__ glb_lb, const float* __restrict__ glb_ub,
                        const float* __restrict__ tw) {
    int b = blockIdx.y;
    int tid = threadIdx.x;
    int wq = tid >> 5, lane = tid & 31;
    int k = blockIdx.x * 8 + wq;
    __shared__ float s_lb[Mw], s_w[Mw], s_tw[Mw];
    __shared__ int   s_i0[32];
    __shared__ float s_w1[32];
    __shared__ float4 s_s1[32][32];
    float T2 = g_T2[b], T1 = g_T1[b];
    for (int i = tid; i < Mw; i += 256) {
        float lb = glb_lb[b * Mw + i] * T2;
        float ub = glb_ub[b * Mw + i] * T2;
        s_lb[i] = lb; s_w[i] = ub - lb; s_tw[i] = tw[b * Mw + i];
    }
    __syncthreads();
    float frk = (float)k / 95.0f;
    float invT2 = 1.f / T2, invT1 = 1.f / T1;
    const float* s2b = s2f + (size_t)b * N2 * Dd;
    const float* s1b = s1f + (size_t)b * N1 * Dd;
    int i0p = -1;
    float4 f0v = make_float4(0.f, 0.f, 0.f, 0.f), f1v = f0v;
    for (int mc = 0; mc < Mw; mc += 32) {
        __syncthreads();
        if (tid < 32) {
            float pos = s_tw[mc + tid] * invT1;
            float x = fminf(fmaxf(pos, 0.f), 1.f) * (float)(N1 - 1);
            int i0 = min(max((int)x, 0), N1 - 2);
            s_i0[tid] = i0;
            s_w1[tid] = x - (float)i0;
        }
        __syncthreads();
        for (int idx = tid; idx < 1024; idx += 256) {
            int ml = idx >> 5, l4 = idx & 31;
            const float4* r0 = (const float4*)(s1b + (size_t)s_i0[ml] * Dd);
            float4 f0 = r0[l4], f1 = r0[32 + l4];
            float ww = s_w1[ml];
            float4 o;
            o.x = f0.x + ww * (f1.x - f0.x);
            o.y = f0.y + ww * (f1.y - f0.y);
            o.z = f0.z + ww * (f1.z - f0.z);
            o.w = f0.w + ww * (f1.w - f0.w);
            s_s1[ml][l4] = o;
        }
        __syncthreads();
        for (int m0 = 0; m0 < 32; m0 += 4) {
            float acc[4], tks[4];
            #pragma unroll
            for (int u = 0; u < 4; u++) {
                int m = mc + m0 + u;
                float tk = s_lb[m] + s_w[m] * frk;
                tks[u] = tk;
                float x = fminf(fmaxf(tk * invT2, 0.f), 1.f) * (float)(N2 - 1);
                int i0 = min(max((int)x, 0), N2 - 2);
                float w = x - (float)i0;
                if (i0 != i0p) {
                    f0v = *((const float4*)(s2b + (size_t)i0 * Dd) + lane);
                    f1v = *((const float4*)(s2b + (size_t)(i0 + 1) * Dd) + lane);
                    i0p = i0;
                }
                float4 s1v = s_s1[m0 + u][lane];
                float d0 = s1v.x - (f0v.x + w * (f1v.x - f0v.x));
                float d1 = s1v.y - (f0v.y + w * (f1v.y - f0v.y));
                float d2 = s1v.z - (f0v.z + w * (f1v.z - f0v.z));
                float d3 = s1v.w - (f0v.w + w * (f1v.w - f0v.w));
                acc[u] = fmaf(d0, d0, fmaf(d1, d1, fmaf(d2, d2, d3 * d3)));
            }
            for (int o = 16; o; o >>= 1) {
                #pragma unroll
                for (int u = 0; u < 4; u++)
                    acc[u] += __shfl_xor_sync(FULLM, acc[u], o);
            }
            if (lane == 0) {
                #pragma unroll
                for (int u = 0; u < 4; u++) {
                    int m = mc + m0 + u;
                    float twm = s_tw[m];
                    float wt = 0.f;
                    if (m > 0) wt += twm - s_tw[m - 1];
                    if (m < Mw - 1) wt += s_tw[m + 1] - twm;
                    wt *= 0.5f;
                    float node = acc[u] * wt;
                    float tk = tks[u];
                    if (m == 0) node += BARRIERc * tk * tk;
                    if (m == Mw - 1) { float dd = tk - T2; node += BARRIERc * dd * dd; }
                    g_node[b][m][k] = node;
                }
            }
        }
    }
}

// ---------------- edge cost ----------------
__device__ __forceinline__ float edge_fn(float slope, float gub, float rwd) {
    float d1 = slope - 1.f;
    float n1 = fminf(slope, 0.f);
    float r2 = fmaxf(slope - gub, 0.f);
    float pen = fmaf(n1, n1, r2 * r2);
    return fmaf(BARRIERc, pen, rwd * d1 * d1);
}

// general windowed softmin (cold path)
__device__ __forceinline__ float softmin_win(
    const float* __restrict__ sa, const float* __restrict__ sfrac,
    int jlo, int jhi, float tref, float sgn, float invd,
    float lbp, float wp, float gub, float rwd) {
    float mval = INFf, ssum = 0.f;
    for (int j = jlo; j <= jhi; j++) {
        float tpj = lbp + wp * sfrac[j];
        float slope = sgn * (tref - tpj) * invd;
        float e = edge_fn(slope, gub, rwd);
        float xv = sa[j] + e;
        float dlt = xv - mval;
        float tt = ex2a(-fabsf(dlt) * IG2);
        if (dlt < 0.f) { ssum = fmaf(ssum, tt, 1.f); mval = xv; }
        else           { ssum += tt; }
    }
    return mval - GLN2 * lg2a(ssum);
}

// 2-candidate softmin (y may be INF)
__device__ __forceinline__ float sm2(float x, float y) {
    float mv = fminf(x, y);
    float ss = 1.f + ex2a(-fabsf(x - y) * IG2);
    return mv - GLN2 * lg2a(ss);
}

// ---------------- kernel 3: single-warp scans, 2-wide window, deferred verify ----------------
// layout: lane holds k = 3*lane + r
__global__ void k3_scan(const float* __restrict__ tw, const float* __restrict__ reg_wt,
                        const float* __restrict__ lgu, const float* __restrict__ glb_lb,
                        const float* __restrict__ glb_ub) {
    int dir = blockIdx.x, b = blockIdx.y;
    int lane = threadIdx.x;
    __shared__ float s_lb[Mw], s_w[Mw], s_tw[Mw], s_frac[Kd], s_a[Kd];
    float T2 = g_T2[b];
    for (int i = lane; i < Mw; i += 32) {
        float lb = glb_lb[b * Mw + i] * T2;
        float ub = glb_ub[b * Mw + i] * T2;
        s_lb[i] = lb; s_w[i] = ub - lb; s_tw[i] = tw[b * Mw + i];
    }
    for (int i = lane; i < Kd; i += 32) s_frac[i] = (float)i / 95.0f;
    __syncwarp();
    float rw = reg_wt[b], gub = lgu[b];
    float gmin1 = fmaxf(1.f, gub);
    int kb = 3 * lane;
    float fr0 = (float)kb / 95.0f, fr1 = (float)(kb + 1) / 95.0f, fr2 = (float)(kb + 2) / 95.0f;
    bool gl = (lane >= 1), gr = (lane <= 30);
    bool allok = true;

    if (dir == 0) {
        // ================ forward fast path (no branches in loop) ================
        {
            float a0 = g_node[b][0][kb], a1 = g_node[b][0][kb + 1], a2 = g_node[b][0][kb + 2];
            g_alpha[b][0][kb] = a0; g_alpha[b][0][kb + 1] = a1; g_alpha[b][0][kb + 2] = a2;
            float mina = o2f(__reduce_min_sync(FULLM, f2o(fminf(fminf(a0, a1), a2))));
            float maxa = o2f(__reduce_max_sync(FULLM, f2o(fmaxf(fmaxf(a0, a1), a2))));
            float nn0 = g_node[b][1][kb], nn1 = g_node[b][1][kb + 1], nn2 = g_node[b][1][kb + 2];
            int i2 = min(2, Mw - 1);
            float nf0 = g_node[b][i2][kb], nf1 = g_node[b][i2][kb + 1], nf2 = g_node[b][i2][kb + 2];
            float lbp = s_lb[0], wp = s_w[0], twp = s_tw[0];
            for (int i = 0; i < Mw - 1; i++) {
                float lbn = s_lb[i + 1], wn = s_w[i + 1], twn = s_tw[i + 1];
                float dtw = twn - twp;
                float invd = __fdividef(1.f, dtw);
                float rwd = rw * dtw;
                int ip = min(i + 3, Mw - 1);
                float nl0 = g_node[b][ip][kb], nl1 = g_node[b][ip][kb + 1], nl2 = g_node[b][ip][kb + 2];
                float sinv = wp * invd * (1.0f / 95.0f);
                float e1 = rwd;                       // delta=0 (slope 0); valid for gub>=0
                float e2 = edge_fn(sinv, gub, rwd);   // delta=1
                float p2 = __shfl_up_sync(FULLM, a2, 1);
                // k gets j=k (e1) and j=k-1 (e2)
                float an0 = nn0 + sm2(a0 + e1, gl ? p2 + e2 : INFf);
                float an1 = nn1 + sm2(a1 + e1, a0 + e2);
                float an2 = nn2 + sm2(a2 + e1, a1 + e2);
                // deferred verification (off critical path)
                float thr = maxa - mina + 15.f;
                bool okstep = (lbn == lbp) && (wn == wp) && (wp > 0.f) && (gub >= 0.f)
                           && (edge_fn(-sinv, gub, rwd) >= thr)
                           && (edge_fn(2.f * sinv, gub, rwd) >= thr)
                           && (2.f * sinv >= gmin1);
                allok = allok && okstep;
                g_alpha[b][i + 1][kb] = an0; g_alpha[b][i + 1][kb + 1] = an1; g_alpha[b][i + 1][kb + 2] = an2;
                mina = o2f(__reduce_min_sync(FULLM, f2o(fminf(fminf(an0, an1), an2))));
                maxa = o2f(__reduce_max_sync(FULLM, f2o(fmaxf(fmaxf(an0, an1), an2))));
                a0 = an0; a1 = an1; a2 = an2;
                nn0 = nf0; nn1 = nf1; nn2 = nf2;
                nf0 = nl0; nf1 = nl1; nf2 = nl2;
                lbp = lbn; wp = wn; twp = twn;
            }
        }
        // ================ cold general redo ================
        if (!__all_sync(FULLM, allok)) {
            float a0 = g_node[b][0][kb], a1 = g_node[b][0][kb + 1], a2 = g_node[b][0][kb + 2];
            g_alpha[b][0][kb] = a0; g_alpha[b][0][kb + 1] = a1; g_alpha[b][0][kb + 2] = a2;
            float mina = o2f(__reduce_min_sync(FULLM, f2o(fminf(fminf(a0, a1), a2))));
            float maxa = o2f(__reduce_max_sync(FULLM, f2o(fmaxf(fmaxf(a0, a1), a2))));
            float lbp = s_lb[0], wp = s_w[0], twp = s_tw[0];
            for (int i = 0; i < Mw - 1; i++) {
                float lbn = s_lb[i + 1], wn = s_w[i + 1], twn = s_tw[i + 1];
                float dtw = twn - twp;
                float invd = __fdividef(1.f, dtw);
                float rwd = rw * dtw;
                s_a[kb] = a0; s_a[kb + 1] = a1; s_a[kb + 2] = a2;
                __syncwarp();
                float marg = sqrta((maxa - mina + 15.f) * (1.f / BARRIERc));
                float inv95wp = __fdividef(95.0f, wp);
                bool degen = !(wp > 0.f);
                float loOff = (gub + marg) * dtw;
                float hiOff = marg * dtw;
                float res[3];
                float frs[3] = {fr0, fr1, fr2};
                #pragma unroll
                for (int r = 0; r < 3; r++) {
                    float tnk = lbn + wn * frs[r];
                    int jlo = max(0, __float2int_ru((tnk - loOff - lbp) * inv95wp));
                    int jhi = min(Kd - 1, __float2int_rd((tnk + hiOff - lbp) * inv95wp));
                    if (degen) { jlo = 0; jhi = Kd - 1; }
                    if (jhi < jlo) { int c = min(Kd - 1, max(0, jlo)); jlo = max(0, c - 1); jhi = min(Kd - 1, c + 1); }
                    res[r] = softmin_win(s_a, s_frac, jlo, jhi, tnk, 1.f, invd, lbp, wp, gub, rwd);
                }
                __syncwarp();
                float an0 = g_node[b][i + 1][kb] + res[0];
                float an1 = g_node[b][i + 1][kb + 1] + res[1];
                float an2 = g_node[b][i + 1][kb + 2] + res[2];
                g_alpha[b][i + 1][kb] = an0; g_alpha[b][i + 1][kb + 1] = an1; g_alpha[b][i + 1][kb + 2] = an2;
                mina = o2f(__reduce_min_sync(FULLM, f2o(fminf(fminf(an0, an1), an2))));
                maxa = o2f(__reduce_max_sync(FULLM, f2o(fmaxf(fmaxf(an0, an1), an2))));
                a0 = an0; a1 = an1; a2 = an2;
                lbp = lbn; wp = wn; twp = twn;
            }
        }
    } else {
        // ================ backward fast path ================
        {
            float a0 = g_node[b][Mw - 1][kb], a1 = g_node[b][Mw - 1][kb + 1], a2 = g_node[b][Mw - 1][kb + 2];
            g_beta[b][Mw - 1][kb] = 0.f; g_beta[b][Mw - 1][kb + 1] = 0.f; g_beta[b][Mw - 1][kb + 2] = 0.f;
            float mina = o2f(__reduce_min_sync(FULLM, f2o(fminf(fminf(a0, a1), a2))));
            float maxa = o2f(__reduce_max_sync(FULLM, f2o(fmaxf(fmaxf(a0, a1), a2))));
            float ni0 = g_node[b][Mw - 2][kb], ni1 = g_node[b][Mw - 2][kb + 1], ni2 = g_node[b][Mw - 2][kb + 2];
            int i3 = max(Mw - 3, 0);
            float nf0 = g_node[b][i3][kb], nf1 = g_node[b][i3][kb + 1], nf2 = g_node[b][i3][kb + 2];
            float lbp = s_lb[Mw - 1], wp = s_w[Mw - 1], twp = s_tw[Mw - 1];
            for (int i = Mw - 2; i >= 0; i--) {
                float lbj = s_lb[i], wj = s_w[i], twj = s_tw[i];
                float dtw = twp - twj;
                float invd = __fdividef(1.f, dtw);
                float rwd = rw * dtw;
                int ip = max(i - 2, 0);
                float nl0 = g_node[b][ip][kb], nl1 = g_node[b][ip][kb + 1], nl2 = g_node[b][ip][kb + 2];
                float sinv = wp * invd * (1.0f / 95.0f);
                float e1 = rwd;
                float e2 = edge_fn(sinv, gub, rwd);
                float n0 = __shfl_down_sync(FULLM, a0, 1);
                // k gets kq=k (e1) and kq=k+1 (e2)
                float bn0 = sm2(a0 + e1, a1 + e2);
                float bn1 = sm2(a1 + e1, a2 + e2);
                float bn2 = sm2(a2 + e1, gr ? n0 + e2 : INFf);
                float thr = maxa - mina + 15.f;
                bool okstep = (lbj == lbp) && (wj == wp) && (wp > 0.f) && (gub >= 0.f)
                           && (edge_fn(-sinv, gub, rwd) >= thr)
                           && (edge_fn(2.f * sinv, gub, rwd) >= thr)
                           && (2.f * sinv >= gmin1);
                allok = allok && okstep;
                g_beta[b][i][kb] = bn0; g_beta[b][i][kb + 1] = bn1; g_beta[b][i][kb + 2] = bn2;
                float c0 = ni0 + bn0, c1 = ni1 + bn1, c2 = ni2 + bn2;
                mina = o2f(__reduce_min_sync(FULLM, f2o(fminf(fminf(c0, c1), c2))));
                maxa = o2f(__reduce_max_sync(FULLM, f2o(fmaxf(fmaxf(c0, c1), c2))));
                a0 = c0; a1 = c1; a2 = c2;
                ni0 = nf0; ni1 = nf1; ni2 = nf2;
                nf0 = nl0; nf1 = nl1; nf2 = nl2;
                lbp = lbj; wp = wj; twp = twj;
            }
        }
        // ================ cold general redo ================
        if (!__all_sync(FULLM, allok)) {
            float a0 = g_node[b][Mw - 1][kb], a1 = g_node[b][Mw - 1][kb + 1], a2 = g_node[b][Mw - 1][kb + 2];
            g_beta[b][Mw - 1][kb] = 0.f; g_beta[b][Mw - 1][kb + 1] = 0.f; g_beta[b][Mw - 1][kb + 2] = 0.f;
            float mina = o2f(__reduce_min_sync(FULLM, f2o(fminf(fminf(a0, a1), a2))));
            float maxa = o2f(__reduce_max_sync(FULLM, f2o(fmaxf(fmaxf(a0, a1), a2))));
            float lbp = s_lb[Mw - 1], wp = s_w[Mw - 1], twp = s_tw[Mw - 1];
            for (int i = Mw - 2; i >= 0; i--) {
                float lbj = s_lb[i], wj = s_w[i], twj = s_tw[i];
                float dtw = twp - twj;
                float invd = __fdividef(1.f, dtw);
                float rwd = rw * dtw;
                s_a[kb] = a0; s_a[kb + 1] = a1; s_a[kb + 2] = a2;
                __syncwarp();
                float marg = sqrta((maxa - mina + 15.f) * (1.f / BARRIERc));
                float inv95wp = __fdividef(95.0f, wp);
                bool degen = !(wp > 0.f);
                float loOff = marg * dtw;
                float hiOff = (gub + marg) * dtw;
                float res[3];
                float frs[3] = {fr0, fr1, fr2};
                #pragma unroll
                for (int r = 0; r < 3; r++) {
                    float tj = lbj + wj * frs[r];
                    int klo = max(0, __float2int_ru((tj - loOff - lbp) * inv95wp));
                    int khi = min(Kd - 1, __float2int_rd((tj + hiOff - lbp) * inv95wp));
                    if (degen) { klo = 0; khi = Kd - 1; }
                    if (khi < klo) { int cc = min(Kd - 1, max(0, klo)); klo = max(0, cc - 1); khi = min(Kd - 1, cc + 1); }
                    res[r] = softmin_win(s_a, s_frac, klo, khi, tj, -1.f, invd, lbp, wp, gub, rwd);
                }
                __syncwarp();
                g_beta[b][i][kb] = res[0]; g_beta[b][i][kb + 1] = res[1]; g_beta[b][i][kb + 2] = res[2];
                float c0 = g_node[b][i][kb] + res[0];
                float c1 = g_node[b][i][kb + 1] + res[1];
                float c2 = g_node[b][i][kb + 2] + res[2];
                mina = o2f(__reduce_min_sync(FULLM, f2o(fminf(fminf(c0, c1), c2))));
                maxa = o2f(__reduce_max_sync(FULLM, f2o(fmaxf(fmaxf(c0, c1), c2))));
                a0 = c0; a1 = c1; a2 = c2;
                lbp = lbj; wp = wj; twp = twj;
            }
        }
    }
}

// ---------------- kernel 4: 8 warps/block ----------------
__global__ void k4_out(const float* __restrict__ glb_lb, const float* __restrict__ glb_ub,
                       float* __restrict__ out) {
    int b = blockIdx.y;
    int wid = threadIdx.x >> 5, lane = threadIdx.x & 31;
    int m = blockIdx.x * 8 + wid;
    float T2 = g_T2[b];
    float lb = glb_lb[b * Mw + m] * T2;
    float ub = glb_ub[b * Mw + m] * T2;
    float w = ub - lb;
    float v[3], ta[3];
    #pragma unroll
    for (int r = 0; r < 3; r++) {
        int k = lane + 32 * r;
        v[r] = g_alpha[b][m][k] + g_beta[b][m][k];
        ta[r] = lb + w * ((float)k / 95.0f);
    }
    float l = fminf(fminf(v[0], v[1]), v[2]);
    float vmin = o2f(__reduce_min_sync(FULLM, f2o(l)));
    float ps = 0.f, pts = 0.f;
    #pragma unroll
    for (int r = 0; r < 3; r++) {
        float p = ex2a((vmin - v[r]) * IG2);
        ps += p;
        pts = fmaf(p, ta[r], pts);
    }
    for (int o = 16; o; o >>= 1) {
        ps += __shfl_xor_sync(FULLM, ps, o);
        pts += __shfl_xor_sync(FULLM, pts, o);
    }
    if (lane == 0) out[b * Mw + m] = pts / ps;
}

extern "C" void kernel_launch(void* const* d_in, const int* in_sizes, int n_in,
                              void* d_out, int out_size) {
    const float* s1f    = (const float*)d_in[0];
    const float* s2f    = (const float*)d_in[1];
    const float* regw   = (const float*)d_in[2];
    const float* glb_lb = (const float*)d_in[3];
    const float* glb_ub = (const float*)d_in[4];
    const float* lgu    = (const float*)d_in[5];
    const float* t1     = (const float*)d_in[6];
    const float* t2     = (const float*)d_in[7];
    const float* twf    = (const float*)d_in[8];
    float* out = (float*)d_out;

    k0_maxes<<<Bn, 256>>>(t1, t2);
    k2_node<<<dim3(Kd / 8, Bn), 256>>>(s1f, s2f, glb_lb, glb_ub, twf);
    k3_scan<<<dim3(2, Bn), 32>>>(twf, regw, lgu, glb_lb, glb_ub);
    k4_out<<<dim3(Mw / 8, Bn), 256>>>(glb_lb, glb_ub, out);
}